// round 4
// baseline (speedup 1.0000x reference)
#include <cuda_runtime.h>
#include <cuda_bf16.h>
#include <math.h>
#include <stdint.h>

// Problem constants: B=8, N=1024, Fin=512, Fout=512, H=8, dh=64
#define BATCH 8
#define NN    1024
#define FIN   512
#define FOUT  512
#define HEADS 8
#define DH    64
#define ALPHA_LR 0.2f

// ---------------- device scratch ----------------
__device__ __nv_bfloat16 g_xh[BATCH * NN * FIN];
__device__ __nv_bfloat16 g_xl[BATCH * NN * FIN];
__device__ __nv_bfloat16 g_wh[FIN * FOUT];
__device__ __nv_bfloat16 g_wl[FIN * FOUT];
__device__ __nv_bfloat16 g_hh[BATCH * NN * FOUT];    // h hi (bf16)
__device__ __nv_bfloat16 g_hl[BATCH * NN * FOUT];    // h lo (bf16)
__device__ float         g_ssrc[BATCH * HEADS * NN];
__device__ float         g_sdst[BATCH * HEADS * NN];
__device__ unsigned      g_adjbits[BATCH * NN * (NN / 32)];

// ---------------- PTX helpers ----------------
static __device__ __forceinline__ uint32_t smem_u32(const void* p) {
    return (uint32_t)__cvta_generic_to_shared(p);
}
static __device__ __forceinline__ void ldsm_x4(uint32_t* r, uint32_t a) {
    asm volatile("ldmatrix.sync.aligned.m8n8.x4.shared.b16 {%0,%1,%2,%3}, [%4];"
        : "=r"(r[0]), "=r"(r[1]), "=r"(r[2]), "=r"(r[3]) : "r"(a));
}
static __device__ __forceinline__ void ldsm_x4_t(uint32_t* r, uint32_t a) {
    asm volatile("ldmatrix.sync.aligned.m8n8.x4.trans.shared.b16 {%0,%1,%2,%3}, [%4];"
        : "=r"(r[0]), "=r"(r[1]), "=r"(r[2]), "=r"(r[3]) : "r"(a));
}
static __device__ __forceinline__ void mma16816(float* d, const uint32_t* a,
                                                uint32_t b0, uint32_t b1) {
    asm volatile(
        "mma.sync.aligned.m16n8k16.row.col.f32.bf16.bf16.f32 "
        "{%0,%1,%2,%3}, {%4,%5,%6,%7}, {%8,%9}, {%0,%1,%2,%3};"
        : "+f"(d[0]), "+f"(d[1]), "+f"(d[2]), "+f"(d[3])
        : "r"(a[0]), "r"(a[1]), "r"(a[2]), "r"(a[3]), "r"(b0), "r"(b1));
}

// ---------------------------------------------------------------------------
// C0: split X and W into bf16 hi/lo
// ---------------------------------------------------------------------------
__global__ __launch_bounds__(256) void conv_xw(const float* __restrict__ X,
                                               const float* __restrict__ W)
{
    int idx = blockIdx.x * 256 + threadIdx.x;
    const int NX = BATCH * NN * FIN;
    if (idx < NX) {
        float v = X[idx];
        __nv_bfloat16 hi = __float2bfloat16_rn(v);
        g_xh[idx] = hi;
        g_xl[idx] = __float2bfloat16_rn(v - __bfloat162float(hi));
    } else {
        int wi = idx - NX;
        if (wi < FIN * FOUT) {
            float v = W[wi];
            __nv_bfloat16 hi = __float2bfloat16_rn(v);
            g_wh[wi] = hi;
            g_wl[wi] = __float2bfloat16_rn(v - __bfloat162float(hi));
        }
    }
}

// ---------------------------------------------------------------------------
// C1: pack adjacency to bitmask
// ---------------------------------------------------------------------------
__global__ __launch_bounds__(256) void adj_pack(const int* __restrict__ adj)
{
    int e = blockIdx.x * 256 + threadIdx.x;
    unsigned m = __ballot_sync(0xffffffffu, adj[e] > 0);
    if ((threadIdx.x & 31) == 0) g_adjbits[e >> 5] = m;
}

// ---------------------------------------------------------------------------
// K1: split-bf16 MMA GEMM  h = X @ W + b  (3 terms, single staging pass,
// double-buffered, one sync per k-chunk). Epilogue: write g_hh/g_hl and
// fused attention scores (block owns 2 complete heads x 128 rows).
// smem layout (dynamic):
//   Ah: 2 bufs x 10240B   @ 0
//   Al: 2 bufs x 10240B   @ 20480
//   Bh: 2 bufs x 8704B    @ 40960
//   Bl: 2 bufs x 8704B    @ 58368
//   att tile (256 f)      @ 75776
//   dt 128x129 f32 (66048B) overlaps buffers after last sync
// ---------------------------------------------------------------------------
#define GM_AH 0
#define GM_AL 20480
#define GM_BH 40960
#define GM_BL 58368
#define GM_ATT 75776
#define GEMM_SMEM (GM_ATT + 1024)

__global__ __launch_bounds__(256) void gemm_mma(const float* __restrict__ bias,
                                                const float* __restrict__ att)
{
    extern __shared__ char sp[];
    const int tid = threadIdx.x;
    const int w = tid >> 5, lane = tid & 31;
    const int wm = w >> 2, wn = w & 3;          // 2m x 4n warps, warp m64 x n32
    const int bm = blockIdx.y * 128, bn = blockIdx.x * 128;

    float* sAtt = (float*)(sp + GM_ATT);
    sAtt[tid] = att[blockIdx.x * 256 + tid];

    float acc[4][4][4];
#pragma unroll
    for (int i = 0; i < 4; i++)
#pragma unroll
        for (int j = 0; j < 4; j++)
#pragma unroll
            for (int r = 0; r < 4; r++) acc[i][j][r] = 0.f;

    // -------- staging helper (k-chunk of 32) --------
    auto stage = [&](int kc, int buf) {
#pragma unroll
        for (int r = 0; r < 2; r++) {
            int u = tid + r * 256;
            int row = u >> 2, q = u & 3;
            size_t src = (size_t)(bm + row) * FIN + kc * 32 + q * 8;
            *(uint4*)(sp + GM_AH + buf * 10240 + row * 80 + q * 16) =
                *(const uint4*)&g_xh[src];
            *(uint4*)(sp + GM_AL + buf * 10240 + row * 80 + q * 16) =
                *(const uint4*)&g_xl[src];
        }
#pragma unroll
        for (int r = 0; r < 2; r++) {
            int u = tid + r * 256;
            int kr = u >> 4, c = u & 15;
            size_t src = (size_t)(kc * 32 + kr) * FOUT + bn + c * 8;
            *(uint4*)(sp + GM_BH + buf * 8704 + kr * 272 + c * 16) =
                *(const uint4*)&g_wh[src];
            *(uint4*)(sp + GM_BL + buf * 8704 + kr * 272 + c * 16) =
                *(const uint4*)&g_wl[src];
        }
    };

    stage(0, 0);
    __syncthreads();

#pragma unroll 1
    for (int kc = 0; kc < FIN / 32; kc++) {
        const int buf = kc & 1;
        if (kc < FIN / 32 - 1) stage(kc + 1, buf ^ 1);

        const char* pAh = sp + GM_AH + buf * 10240;
        const char* pAl = sp + GM_AL + buf * 10240;
        const char* pBh = sp + GM_BH + buf * 8704;
        const char* pBl = sp + GM_BL + buf * 8704;

#pragma unroll
        for (int k16 = 0; k16 < 2; k16++) {
            const int krow = k16 * 16 + (lane & 15);
            uint32_t bh4[2][4], bl4[2][4];
#pragma unroll
            for (int p = 0; p < 2; p++) {
                int col = wn * 32 + p * 16 + (lane >> 4) * 8;
                ldsm_x4_t(bh4[p], smem_u32(pBh + (krow * 136 + col) * 2));
                ldsm_x4_t(bl4[p], smem_u32(pBl + (krow * 136 + col) * 2));
            }
#pragma unroll
            for (int mt = 0; mt < 4; mt++) {
                int arow = (wm * 64 + mt * 16 + (lane & 15)) * 40 +
                           k16 * 16 + (lane >> 4) * 8;
                uint32_t ah[4], al[4];
                ldsm_x4(ah, smem_u32(pAh + arow * 2));
                ldsm_x4(al, smem_u32(pAl + arow * 2));
#pragma unroll
                for (int p = 0; p < 2; p++) {
                    mma16816(acc[mt][2 * p],     ah, bh4[p][0], bh4[p][1]);
                    mma16816(acc[mt][2 * p],     ah, bl4[p][0], bl4[p][1]);
                    mma16816(acc[mt][2 * p],     al, bh4[p][0], bh4[p][1]);
                    mma16816(acc[mt][2 * p + 1], ah, bh4[p][2], bh4[p][3]);
                    mma16816(acc[mt][2 * p + 1], ah, bl4[p][2], bl4[p][3]);
                    mma16816(acc[mt][2 * p + 1], al, bh4[p][2], bh4[p][3]);
                }
            }
        }
        __syncthreads();
    }

    // -------- epilogue: bias, write g_hh/g_hl, stash biased values in dt ----
    float* dt = (float*)sp;                 // 128 x 129 fp32 (buffers dead)
    const int g = lane >> 2, t = lane & 3;
#pragma unroll
    for (int mt = 0; mt < 4; mt++) {
        const int r0 = wm * 64 + mt * 16 + g;
        const int r1 = r0 + 8;
#pragma unroll
        for (int nt = 0; nt < 4; nt++) {
            int colL = wn * 32 + nt * 8 + 2 * t;
            float2 bv = *(const float2*)&bias[bn + colL];
            float c0 = acc[mt][nt][0] + bv.x;
            float c1 = acc[mt][nt][1] + bv.y;
            float c2 = acc[mt][nt][2] + bv.x;
            float c3 = acc[mt][nt][3] + bv.y;
            dt[r0 * 129 + colL] = c0; dt[r0 * 129 + colL + 1] = c1;
            dt[r1 * 129 + colL] = c2; dt[r1 * 129 + colL + 1] = c3;
            __nv_bfloat162 h0, h1, l0, l1;
            h0.x = __float2bfloat16_rn(c0); h0.y = __float2bfloat16_rn(c1);
            h1.x = __float2bfloat16_rn(c2); h1.y = __float2bfloat16_rn(c3);
            l0.x = __float2bfloat16_rn(c0 - __bfloat162float(h0.x));
            l0.y = __float2bfloat16_rn(c1 - __bfloat162float(h0.y));
            l1.x = __float2bfloat16_rn(c2 - __bfloat162float(h1.x));
            l1.y = __float2bfloat16_rn(c3 - __bfloat162float(h1.y));
            size_t d0 = (size_t)(bm + r0) * FOUT + bn + colL;
            size_t d1 = (size_t)(bm + r1) * FOUT + bn + colL;
            *(__nv_bfloat162*)&g_hh[d0] = h0;
            *(__nv_bfloat162*)&g_hh[d1] = h1;
            *(__nv_bfloat162*)&g_hl[d0] = l0;
            *(__nv_bfloat162*)&g_hl[d1] = l1;
        }
    }
    __syncthreads();

    // -------- fused attention scores for the 2 heads this block owns -------
    {
        const int row = tid >> 1, hloc = tid & 1;
        const int hglob = blockIdx.x * 2 + hloc;
        const float* as = sAtt + hloc * 128;
        float ssum = 0.f, dsum = 0.f;
#pragma unroll 16
        for (int d = 0; d < DH; d++) {
            float v = dt[row * 129 + hloc * 64 + d];
            ssum = fmaf(v, as[d], ssum);
            dsum = fmaf(v, as[64 + d], dsum);
        }
        const int bq = bm >> 10;
        const int n = (bm & 1023) + row;
        g_ssrc[(bq * HEADS + hglob) * NN + n] = ssum;
        g_sdst[(bq * HEADS + hglob) * NN + n] = dsum;
    }
}

// ---------------------------------------------------------------------------
// K3: fused masked softmax + PV (split-bf16 MMA) + ELU
// block = (b, h, 128 i-rows); 8 warps as 4m x 2n (warp m32 x n32).
// j-tiles of 32, double-buffered P(hi/lo)+V(hi/lo), ONE sync per tile:
//   stage(jt+1) + genP(jt+1) issued BEFORE the MMAs of jt -> overlap.
// fp32 side-sum denominator (no ones-column MMA).
// smem layout (dynamic):
//   Ph: 2 x 10240 @ 0        Pl: 2 x 10240 @ 20480
//   Vh: 2 x 4608  @ 40960    Vl: 2 x 4608  @ 50176
//   ss: 4096      @ 59392    sden: 512     @ 63488
// ---------------------------------------------------------------------------
#define AT_PH 0
#define AT_PL 20480
#define AT_VH 40960
#define AT_VL 50176
#define AT_SS 59392
#define AT_SDEN 63488
#define ATTN_SMEM (AT_SDEN + 512)

__global__ __launch_bounds__(256) void attn_mma(float* __restrict__ out)
{
    extern __shared__ char sp[];
    const int b = blockIdx.z, h = blockIdx.y;
    const int i0 = blockIdx.x * 128;
    const int tid = threadIdx.x;
    const int w = tid >> 5, lane = tid & 31;
    const int wm = w & 3, wn = w >> 2;          // 4m x 2n warps, warp m32 x n32
    const int bh = b * HEADS + h;

    float* ssp  = (float*)(sp + AT_SS);
    float* sden = (float*)(sp + AT_SDEN);
    *(float4*)&ssp[tid * 4] = *(const float4*)&g_ssrc[bh * NN + tid * 4];

    const int pi = tid >> 1;                    // row 0..127
    const int jh = tid & 1;                     // which 16 j's of the tile
    const float sd = g_sdst[bh * NN + i0 + pi];
    const unsigned* mrow = g_adjbits + (size_t)(b * NN + i0 + pi) * (NN / 32);
    float den = 0.f;

    float acc[2][4][4];
#pragma unroll
    for (int i = 0; i < 2; i++)
#pragma unroll
        for (int j = 0; j < 4; j++)
#pragma unroll
            for (int r = 0; r < 4; r++) acc[i][j][r] = 0.f;

    // V stage: 32 j-rows x 64 d, one uint4/thread per kind
    auto stageV = [&](int jt, int buf) {
        int k = tid >> 3, c = tid & 7;
        size_t src = (size_t)(b * NN + jt * 32 + k) * FOUT + h * DH + c * 8;
        *(uint4*)(sp + AT_VH + buf * 4608 + k * 144 + c * 16) =
            *(const uint4*)&g_hh[src];
        *(uint4*)(sp + AT_VL + buf * 4608 + k * 144 + c * 16) =
            *(const uint4*)&g_hl[src];
    };
    // P gen: row pi, 16 j's, masked leakyrelu+exp, split hi/lo, fp32 den
    auto genP = [&](int jt, int buf) {
        const unsigned mw = mrow[jt];
        char* phb = sp + AT_PH + buf * 10240;
        char* plb = sp + AT_PL + buf * 10240;
        const int jb = jh * 16;
#pragma unroll
        for (int q = 0; q < 16; q += 2) {
            float2 s2 = *(const float2*)&ssp[jt * 32 + jb + q];
            float e0 = sd + s2.x; e0 = fmaxf(e0, ALPHA_LR * e0);
            float e1 = sd + s2.y; e1 = fmaxf(e1, ALPHA_LR * e1);
            float p0 = ((mw >> (jb + q)) & 1u)     ? __expf(e0) : 0.f;
            float p1 = ((mw >> (jb + q + 1)) & 1u) ? __expf(e1) : 0.f;
            den += p0 + p1;
            __nv_bfloat162 hh, ll;
            hh.x = __float2bfloat16_rn(p0);
            hh.y = __float2bfloat16_rn(p1);
            ll.x = __float2bfloat16_rn(p0 - __bfloat162float(hh.x));
            ll.y = __float2bfloat16_rn(p1 - __bfloat162float(hh.y));
            *(__nv_bfloat162*)(phb + (pi * 40 + jb + q) * 2) = hh;
            *(__nv_bfloat162*)(plb + (pi * 40 + jb + q) * 2) = ll;
        }
    };

    __syncthreads();           // ssp visible
    stageV(0, 0);
    genP(0, 0);
    __syncthreads();

#pragma unroll 1
    for (int jt = 0; jt < NN / 32; jt++) {
        const int buf = jt & 1;
        if (jt < NN / 32 - 1) { stageV(jt + 1, buf ^ 1); genP(jt + 1, buf ^ 1); }

        const char* phb = sp + AT_PH + buf * 10240;
        const char* plb = sp + AT_PL + buf * 10240;
        const char* vhb = sp + AT_VH + buf * 4608;
        const char* vlb = sp + AT_VL + buf * 4608;

#pragma unroll
        for (int kc = 0; kc < 2; kc++) {
            const int krow = kc * 16 + (lane & 15);
            uint32_t bh4[2][4], bl4[2][4];
#pragma unroll
            for (int p = 0; p < 2; p++) {
                int col = wn * 32 + p * 16 + (lane >> 4) * 8;
                ldsm_x4_t(bh4[p], smem_u32(vhb + (krow * 72 + col) * 2));
                ldsm_x4_t(bl4[p], smem_u32(vlb + (krow * 72 + col) * 2));
            }
#pragma unroll
            for (int mt = 0; mt < 2; mt++) {
                int arow = (wm * 32 + mt * 16 + (lane & 15)) * 40 +
                           kc * 16 + (lane >> 4) * 8;
                uint32_t ah[4], al[4];
                ldsm_x4(ah, smem_u32(phb + arow * 2));
                ldsm_x4(al, smem_u32(plb + arow * 2));
#pragma unroll
                for (int p = 0; p < 2; p++) {
                    mma16816(acc[mt][2 * p],     ah, bh4[p][0], bh4[p][1]);
                    mma16816(acc[mt][2 * p],     ah, bl4[p][0], bl4[p][1]);
                    mma16816(acc[mt][2 * p],     al, bh4[p][0], bh4[p][1]);
                    mma16816(acc[mt][2 * p + 1], ah, bh4[p][2], bh4[p][3]);
                    mma16816(acc[mt][2 * p + 1], ah, bl4[p][2], bl4[p][3]);
                    mma16816(acc[mt][2 * p + 1], al, bh4[p][2], bh4[p][3]);
                }
            }
        }
        __syncthreads();
    }

    // denominator: combine the two 16-j partials per row
    if (jh == 0) sden[pi] = den;
    __syncthreads();
    if (jh == 1) sden[pi] += den;
    __syncthreads();

    // epilogue: normalize, ELU, store
    const int g = lane >> 2, t = lane & 3;
#pragma unroll
    for (int mt = 0; mt < 2; mt++) {
        const int r0 = wm * 32 + mt * 16 + g;
        const int r1 = r0 + 8;
        const float inv0 = 1.f / sden[r0];
        const float inv1 = 1.f / sden[r1];
#pragma unroll
        for (int nt = 0; nt < 4; nt++) {
            int col = h * DH + wn * 32 + nt * 8 + 2 * t;
            float o0 = acc[mt][nt][0] * inv0; o0 = (o0 > 0.f) ? o0 : expm1f(o0);
            float o1 = acc[mt][nt][1] * inv0; o1 = (o1 > 0.f) ? o1 : expm1f(o1);
            float o2 = acc[mt][nt][2] * inv1; o2 = (o2 > 0.f) ? o2 : expm1f(o2);
            float o3 = acc[mt][nt][3] * inv1; o3 = (o3 > 0.f) ? o3 : expm1f(o3);
            *(float2*)&out[(size_t)(b * NN + i0 + r0) * FOUT + col] =
                make_float2(o0, o1);
            *(float2*)&out[(size_t)(b * NN + i0 + r1) * FOUT + col] =
                make_float2(o2, o3);
        }
    }
}

// ---------------------------------------------------------------------------
extern "C" void kernel_launch(void* const* d_in, const int* in_sizes, int n_in,
                              void* d_out, int out_size)
{
    const float* x   = (const float*)d_in[0];   // (8,1024,512)
    const int*   adj = (const int*)d_in[1];     // (8,1024,1024)
    const float* Ww  = (const float*)d_in[2];   // (512,512)
    const float* Wb  = (const float*)d_in[3];   // (512,)
    const float* att = (const float*)d_in[4];   // (8,128)
    float* out = (float*)d_out;                 // (8,1024,512)

    cudaFuncSetAttribute(gemm_mma, cudaFuncAttributeMaxDynamicSharedMemorySize,
                         GEMM_SMEM);
    cudaFuncSetAttribute(attn_mma, cudaFuncAttributeMaxDynamicSharedMemorySize,
                         ATTN_SMEM);

    const int nconv = BATCH * NN * FIN + FIN * FOUT;
    conv_xw<<<(nconv + 255) / 256, 256>>>(x, Ww);
    adj_pack<<<(BATCH * NN * NN) / 256, 256>>>(adj);
    gemm_mma<<<dim3(FOUT / 128, (BATCH * NN) / 128), 256, GEMM_SMEM>>>(Wb, att);
    attn_mma<<<dim3(NN / 128, HEADS, BATCH), 256, ATTN_SMEM>>>(out);
}

// round 7
// speedup vs baseline: 1.6251x; 1.6251x over previous
#include <cuda_runtime.h>
#include <cuda_bf16.h>
#include <math.h>
#include <stdint.h>

// Problem constants: B=8, N=1024, Fin=512, Fout=512, H=8, dh=64
#define BATCH 8
#define NN    1024
#define FIN   512
#define FOUT  512
#define HEADS 8
#define DH    64
#define ALPHA_LR 0.2f

// ---------------- device scratch ----------------
__device__ __nv_bfloat16 g_xh[BATCH * NN * FIN];
__device__ __nv_bfloat16 g_xl[BATCH * NN * FIN];
__device__ __nv_bfloat16 g_wh[FIN * FOUT];
__device__ __nv_bfloat16 g_wl[FIN * FOUT];
__device__ __nv_bfloat16 g_hh[BATCH * NN * FOUT];    // h hi (bf16)
__device__ __nv_bfloat16 g_hl[BATCH * NN * FOUT];    // h lo (bf16)
__device__ float         g_ssrc[BATCH * HEADS * NN];
__device__ float         g_sdst[BATCH * HEADS * NN];
__device__ unsigned      g_adjbits[BATCH * NN * (NN / 32)];

// ---------------- PTX helpers ----------------
static __device__ __forceinline__ uint32_t smem_u32(const void* p) {
    return (uint32_t)__cvta_generic_to_shared(p);
}
static __device__ __forceinline__ void ldsm_x4(uint32_t* r, uint32_t a) {
    asm volatile("ldmatrix.sync.aligned.m8n8.x4.shared.b16 {%0,%1,%2,%3}, [%4];"
        : "=r"(r[0]), "=r"(r[1]), "=r"(r[2]), "=r"(r[3]) : "r"(a));
}
static __device__ __forceinline__ void ldsm_x4_t(uint32_t* r, uint32_t a) {
    asm volatile("ldmatrix.sync.aligned.m8n8.x4.trans.shared.b16 {%0,%1,%2,%3}, [%4];"
        : "=r"(r[0]), "=r"(r[1]), "=r"(r[2]), "=r"(r[3]) : "r"(a));
}
static __device__ __forceinline__ void mma16816(float* d, const uint32_t* a,
                                                uint32_t b0, uint32_t b1) {
    asm volatile(
        "mma.sync.aligned.m16n8k16.row.col.f32.bf16.bf16.f32 "
        "{%0,%1,%2,%3}, {%4,%5,%6,%7}, {%8,%9}, {%0,%1,%2,%3};"
        : "+f"(d[0]), "+f"(d[1]), "+f"(d[2]), "+f"(d[3])
        : "r"(a[0]), "r"(a[1]), "r"(a[2]), "r"(a[3]), "r"(b0), "r"(b1));
}
static __device__ __forceinline__ void cp16(uint32_t dst, const void* src) {
    asm volatile("cp.async.cg.shared.global [%0], [%1], 16;"
        :: "r"(dst), "l"(src) : "memory");
}
static __device__ __forceinline__ void cp4(uint32_t dst, const void* src) {
    asm volatile("cp.async.ca.shared.global [%0], [%1], 4;"
        :: "r"(dst), "l"(src) : "memory");
}
#define CP_COMMIT() asm volatile("cp.async.commit_group;" ::: "memory")
#define CP_WAIT(n)  asm volatile("cp.async.wait_group %0;" :: "n"(n) : "memory")

// pack two floats to bf16x2 (x -> lo, y -> hi)
static __device__ __forceinline__ uint32_t pk2(float x, float y) {
    uint32_t r;
    asm("cvt.rn.bf16x2.f32 %0, %1, %2;" : "=r"(r) : "f"(y), "f"(x));
    return r;
}
// residual lo-part pair given hi pack and original floats
static __device__ __forceinline__ uint32_t lo2(uint32_t hp, float x, float y) {
    float hx = __uint_as_float(hp << 16);
    float hy = __uint_as_float(hp & 0xffff0000u);
    uint32_t r;
    asm("cvt.rn.bf16x2.f32 %0, %1, %2;" : "=r"(r) : "f"(y - hy), "f"(x - hx));
    return r;
}
// masked leakyrelu + exp
static __device__ __forceinline__ float pval(float sd, float s, unsigned m, int bit) {
    float e = sd + s;
    e = fmaxf(e, ALPHA_LR * e);
    float p = __expf(e);
    return ((m >> bit) & 1u) ? p : 0.f;
}

// ---------------------------------------------------------------------------
// C0: split X and W into bf16 hi/lo
// ---------------------------------------------------------------------------
__global__ __launch_bounds__(256) void conv_xw(const float* __restrict__ X,
                                               const float* __restrict__ W)
{
    int idx = blockIdx.x * 256 + threadIdx.x;
    const int NX = BATCH * NN * FIN;
    if (idx < NX) {
        float v = X[idx];
        __nv_bfloat16 hi = __float2bfloat16_rn(v);
        g_xh[idx] = hi;
        g_xl[idx] = __float2bfloat16_rn(v - __bfloat162float(hi));
    } else {
        int wi = idx - NX;
        if (wi < FIN * FOUT) {
            float v = W[wi];
            __nv_bfloat16 hi = __float2bfloat16_rn(v);
            g_wh[wi] = hi;
            g_wl[wi] = __float2bfloat16_rn(v - __bfloat162float(hi));
        }
    }
}

// ---------------------------------------------------------------------------
// C1: pack adjacency to bitmask
// ---------------------------------------------------------------------------
__global__ __launch_bounds__(256) void adj_pack(const int* __restrict__ adj)
{
    int e = blockIdx.x * 256 + threadIdx.x;
    unsigned m = __ballot_sync(0xffffffffu, adj[e] > 0);
    if ((threadIdx.x & 31) == 0) g_adjbits[e >> 5] = m;
}

// ---------------------------------------------------------------------------
// K1: split-bf16 MMA GEMM  h = X @ W + b   (3 terms)
// block tile 128m x 64n (one head wide), 8 warps 4m x 2n (warp m32 x n32).
// k-chunks of 16, 2-buffer prefetch-1 cp.async pipeline.
// Epilogue: bias add, write g_hh/g_hl, fused per-head attention scores.
// smem per buf: Ah 6144 | Al 6144 | Bh 2304 | Bl 2304 = 16896, x2 bufs.
// dt 128x65 fp32 (33280B) reuses buffer space after the mainloop.
// ---------------------------------------------------------------------------
#define GB_SZ 16896
#define GM_ATT (2 * GB_SZ)
#define GEMM_SMEM (GM_ATT + 512)
#define G_NCHUNK (FIN / 16)

__global__ __launch_bounds__(256, 3) void gemm_mma(const float* __restrict__ bias,
                                                   const float* __restrict__ att)
{
    extern __shared__ char sp[];
    const uint32_t sb = smem_u32(sp);
    const int tid = threadIdx.x;
    const int w = tid >> 5, lane = tid & 31;
    const int wm = w & 3, wn = w >> 2;          // 4m x 2n warps
    const int bm = blockIdx.y * 128;
    const int hglob = blockIdx.x;               // one head per block
    const int bn = hglob * 64;

    float* sAtt = (float*)(sp + GM_ATT);
    if (tid < 128) sAtt[tid] = att[hglob * 128 + tid];

    // staging: k-chunk c (16 k's) into buffer buf
    // A: 128 rows x 16k per kind -> 2 cp16/thread
    // B: 16 k-rows x 64n per kind = 2048B per kind = 128 cp16 -> all 256 threads
    auto stage = [&](int c, int buf) {
        const uint32_t bb = sb + buf * GB_SZ;
        int row = tid >> 1, cc = tid & 1;
        size_t asrc = (size_t)(bm + row) * FIN + c * 16 + cc * 8;
        cp16(bb + row * 48 + cc * 16, &g_xh[asrc]);
        cp16(bb + 6144 + row * 48 + cc * 16, &g_xl[asrc]);
        {
            int kind = tid >> 7, u = tid & 127;
            int kr = u >> 3, c2 = u & 7;
            size_t bsrc = (size_t)(c * 16 + kr) * FOUT + bn + c2 * 8;
            cp16(bb + 12288 + kind * 2304 + kr * 144 + c2 * 16,
                 kind ? (const void*)&g_wl[bsrc] : (const void*)&g_wh[bsrc]);
        }
    };

    float acc[2][4][4];
#pragma unroll
    for (int i = 0; i < 2; i++)
#pragma unroll
        for (int j = 0; j < 4; j++)
#pragma unroll
            for (int r = 0; r < 4; r++) acc[i][j][r] = 0.f;

    stage(0, 0); CP_COMMIT();

#pragma unroll 1
    for (int c = 0; c < G_NCHUNK; c++) {
        const int buf = c & 1;
        if (c + 1 < G_NCHUNK) { stage(c + 1, buf ^ 1); CP_COMMIT(); CP_WAIT(1); }
        else CP_WAIT(0);
        __syncthreads();

        const uint32_t bb = sb + buf * GB_SZ;
        uint32_t ah[2][4], al[2][4];
#pragma unroll
        for (int mt = 0; mt < 2; mt++) {
            uint32_t ao = ((wm * 32 + mt * 16 + (lane & 15)) * 24 +
                           (lane >> 4) * 8) * 2;
            ldsm_x4(ah[mt], bb + ao);
            ldsm_x4(al[mt], bb + 6144 + ao);
        }
        const int krow = lane & 15;
#pragma unroll
        for (int p = 0; p < 2; p++) {
            int col = wn * 32 + p * 16 + (lane >> 4) * 8;
            uint32_t bo = (krow * 72 + col) * 2;
            uint32_t bh4[4], bl4[4];
            ldsm_x4_t(bh4, bb + 12288 + bo);
            ldsm_x4_t(bl4, bb + 12288 + 2304 + bo);
#pragma unroll
            for (int mt = 0; mt < 2; mt++) {
                mma16816(acc[mt][2 * p],     ah[mt], bh4[0], bh4[1]);
                mma16816(acc[mt][2 * p],     ah[mt], bl4[0], bl4[1]);
                mma16816(acc[mt][2 * p],     al[mt], bh4[0], bh4[1]);
                mma16816(acc[mt][2 * p + 1], ah[mt], bh4[2], bh4[3]);
                mma16816(acc[mt][2 * p + 1], ah[mt], bl4[2], bl4[3]);
                mma16816(acc[mt][2 * p + 1], al[mt], bh4[2], bh4[3]);
            }
        }
        __syncthreads();
    }

    // -------- epilogue: bias, g_hh/g_hl, dt stash --------
    float* dt = (float*)sp;                      // 128 x 65 fp32
    const int g = lane >> 2, t = lane & 3;
#pragma unroll
    for (int mt = 0; mt < 2; mt++) {
        const int r0 = wm * 32 + mt * 16 + g;
        const int r1 = r0 + 8;
#pragma unroll
        for (int nt = 0; nt < 4; nt++) {
            int colL = wn * 32 + nt * 8 + 2 * t;
            float2 bv = *(const float2*)&bias[bn + colL];
            float c0 = acc[mt][nt][0] + bv.x;
            float c1 = acc[mt][nt][1] + bv.y;
            float c2 = acc[mt][nt][2] + bv.x;
            float c3 = acc[mt][nt][3] + bv.y;
            dt[r0 * 65 + colL] = c0; dt[r0 * 65 + colL + 1] = c1;
            dt[r1 * 65 + colL] = c2; dt[r1 * 65 + colL + 1] = c3;
            __nv_bfloat162 h0, h1, l0, l1;
            h0.x = __float2bfloat16_rn(c0); h0.y = __float2bfloat16_rn(c1);
            h1.x = __float2bfloat16_rn(c2); h1.y = __float2bfloat16_rn(c3);
            l0.x = __float2bfloat16_rn(c0 - __bfloat162float(h0.x));
            l0.y = __float2bfloat16_rn(c1 - __bfloat162float(h0.y));
            l1.x = __float2bfloat16_rn(c2 - __bfloat162float(h1.x));
            l1.y = __float2bfloat16_rn(c3 - __bfloat162float(h1.y));
            size_t d0 = (size_t)(bm + r0) * FOUT + bn + colL;
            size_t d1 = (size_t)(bm + r1) * FOUT + bn + colL;
            *(__nv_bfloat162*)&g_hh[d0] = h0;
            *(__nv_bfloat162*)&g_hh[d1] = h1;
            *(__nv_bfloat162*)&g_hl[d0] = l0;
            *(__nv_bfloat162*)&g_hl[d1] = l1;
        }
    }
    __syncthreads();

    // -------- fused scores for this head --------
    {
        const int row = tid >> 1, half = tid & 1;
        float ssum = 0.f, dsum = 0.f;
#pragma unroll 8
        for (int d = half * 32; d < half * 32 + 32; d++) {
            float v = dt[row * 65 + d];
            ssum = fmaf(v, sAtt[d], ssum);
            dsum = fmaf(v, sAtt[64 + d], dsum);
        }
        ssum += __shfl_xor_sync(0xffffffffu, ssum, 1);
        dsum += __shfl_xor_sync(0xffffffffu, dsum, 1);
        if (half == 0) {
            const int nfull = bm + row;
            const int bq = nfull >> 10, n = nfull & 1023;
            g_ssrc[(bq * HEADS + hglob) * NN + n] = ssum;
            g_sdst[(bq * HEADS + hglob) * NN + n] = dsum;
        }
    }
}

// ---------------------------------------------------------------------------
// K3: fused masked softmax + PV (split-bf16 MMA) + ELU
// block = (b, h, 128 i-rows); 8 warps each own m16 exclusively (warp n64).
// P fragments computed DIRECTLY in mma A registers (no P smem, no A ldsm).
// V hi/lo + mask words via 2-buffer prefetch-1 cp.async pipeline.
// Denominator: per-thread fp32 sum of its own p's, quad shfl reduce.
// smem per buf: Vh 4608 | Vl 4608 | mask 512 = 9728, x2; ss 4096.
// ---------------------------------------------------------------------------
#define AB_SZ 9728
#define AT_SS (2 * AB_SZ)
#define ATTN_SMEM (AT_SS + 4096)

__global__ __launch_bounds__(256, 3) void attn_mma(float* __restrict__ out)
{
    extern __shared__ char sp[];
    const uint32_t sb = smem_u32(sp);
    const int b = blockIdx.z, h = blockIdx.y;
    const int i0 = blockIdx.x * 128;
    const int tid = threadIdx.x;
    const int w = tid >> 5, lane = tid & 31;
    const int bh = b * HEADS + h;

    auto stageV = [&](int jt, int buf) {
        const uint32_t bb = sb + buf * AB_SZ;
        int k = tid >> 3, c = tid & 7;
        size_t src = (size_t)(b * NN + jt * 32 + k) * FOUT + h * DH + c * 8;
        cp16(bb + k * 144 + c * 16, &g_hh[src]);
        cp16(bb + 4608 + k * 144 + c * 16, &g_hl[src]);
        if (tid < 128)
            cp4(bb + 9216 + tid * 4,
                &g_adjbits[(size_t)(b * NN + i0 + tid) * (NN / 32) + jt]);
    };

    const int r = lane >> 2;
    const float sd0 = g_sdst[bh * NN + i0 + w * 16 + r];
    const float sd1 = g_sdst[bh * NN + i0 + w * 16 + r + 8];

    // group 0: ss + V tile 0 + mask 0
    cp16(sb + AT_SS + tid * 16, &g_ssrc[bh * NN + tid * 4]);
    stageV(0, 0); CP_COMMIT();

    float acc[8][4];
#pragma unroll
    for (int i = 0; i < 8; i++)
#pragma unroll
        for (int q = 0; q < 4; q++) acc[i][q] = 0.f;
    float den0 = 0.f, den1 = 0.f;

    const float* ssp = (const float*)(sp + AT_SS);
    const int cq = (lane & 3) * 2;

#pragma unroll 1
    for (int jt = 0; jt < NN / 32; jt++) {
        const int buf = jt & 1;
        if (jt + 1 < NN / 32) { stageV(jt + 1, buf ^ 1); CP_COMMIT(); CP_WAIT(1); }
        else CP_WAIT(0);
        __syncthreads();

        const uint32_t bb = sb + buf * AB_SZ;
        const unsigned mw0 = *(const unsigned*)(sp + buf * AB_SZ + 9216 +
                                                (w * 16 + r) * 4);
        const unsigned mw1 = *(const unsigned*)(sp + buf * AB_SZ + 9216 +
                                                (w * 16 + r + 8) * 4);
#pragma unroll
        for (int kc = 0; kc < 2; kc++) {
            const int jb = jt * 32 + kc * 16;
            float2 sA = *(const float2*)&ssp[jb + cq];
            float2 sB = *(const float2*)&ssp[jb + cq + 8];
            const int sh = kc * 16 + cq;
            float p00 = pval(sd0, sA.x, mw0, sh);
            float p01 = pval(sd0, sA.y, mw0, sh + 1);
            float p10 = pval(sd1, sA.x, mw1, sh);
            float p11 = pval(sd1, sA.y, mw1, sh + 1);
            float p02 = pval(sd0, sB.x, mw0, sh + 8);
            float p03 = pval(sd0, sB.y, mw0, sh + 9);
            float p12 = pval(sd1, sB.x, mw1, sh + 8);
            float p13 = pval(sd1, sB.y, mw1, sh + 9);
            den0 += (p00 + p01) + (p02 + p03);
            den1 += (p10 + p11) + (p12 + p13);
            uint32_t ah[4], al[4];
            ah[0] = pk2(p00, p01); al[0] = lo2(ah[0], p00, p01);
            ah[1] = pk2(p10, p11); al[1] = lo2(ah[1], p10, p11);
            ah[2] = pk2(p02, p03); al[2] = lo2(ah[2], p02, p03);
            ah[3] = pk2(p12, p13); al[3] = lo2(ah[3], p12, p13);

            const int krow = kc * 16 + (lane & 15);
#pragma unroll
            for (int nt2 = 0; nt2 < 4; nt2++) {
                int col = nt2 * 16 + (lane >> 4) * 8;
                uint32_t bo = (krow * 72 + col) * 2;
                uint32_t bh4[4], bl4[4];
                ldsm_x4_t(bh4, bb + bo);
                ldsm_x4_t(bl4, bb + 4608 + bo);
                mma16816(acc[nt2 * 2],     ah, bh4[0], bh4[1]);
                mma16816(acc[nt2 * 2],     ah, bl4[0], bl4[1]);
                mma16816(acc[nt2 * 2],     al, bh4[0], bh4[1]);
                mma16816(acc[nt2 * 2 + 1], ah, bh4[2], bh4[3]);
                mma16816(acc[nt2 * 2 + 1], ah, bl4[2], bl4[3]);
                mma16816(acc[nt2 * 2 + 1], al, bh4[2], bh4[3]);
            }
        }
        __syncthreads();
    }

    // denominator reduce within quads
    den0 += __shfl_xor_sync(0xffffffffu, den0, 1);
    den0 += __shfl_xor_sync(0xffffffffu, den0, 2);
    den1 += __shfl_xor_sync(0xffffffffu, den1, 1);
    den1 += __shfl_xor_sync(0xffffffffu, den1, 2);
    const float inv0 = 1.f / den0;
    const float inv1 = 1.f / den1;

    // epilogue: normalize, ELU, store
    const size_t row0 = (size_t)(b * NN + i0 + w * 16 + r);
    const size_t row1 = row0 + 8;
#pragma unroll
    for (int nt = 0; nt < 8; nt++) {
        int col = h * DH + nt * 8 + cq;
        float o0 = acc[nt][0] * inv0; o0 = (o0 > 0.f) ? o0 : expm1f(o0);
        float o1 = acc[nt][1] * inv0; o1 = (o1 > 0.f) ? o1 : expm1f(o1);
        float o2 = acc[nt][2] * inv1; o2 = (o2 > 0.f) ? o2 : expm1f(o2);
        float o3 = acc[nt][3] * inv1; o3 = (o3 > 0.f) ? o3 : expm1f(o3);
        *(float2*)&out[row0 * FOUT + col] = make_float2(o0, o1);
        *(float2*)&out[row1 * FOUT + col] = make_float2(o2, o3);
    }
}

// ---------------------------------------------------------------------------
extern "C" void kernel_launch(void* const* d_in, const int* in_sizes, int n_in,
                              void* d_out, int out_size)
{
    const float* x   = (const float*)d_in[0];   // (8,1024,512)
    const int*   adj = (const int*)d_in[1];     // (8,1024,1024)
    const float* Ww  = (const float*)d_in[2];   // (512,512)
    const float* Wb  = (const float*)d_in[3];   // (512,)
    const float* att = (const float*)d_in[4];   // (8,128)
    float* out = (float*)d_out;                 // (8,1024,512)

    cudaFuncSetAttribute(gemm_mma, cudaFuncAttributeMaxDynamicSharedMemorySize,
                         GEMM_SMEM);
    cudaFuncSetAttribute(attn_mma, cudaFuncAttributeMaxDynamicSharedMemorySize,
                         ATTN_SMEM);

    const int nconv = BATCH * NN * FIN + FIN * FOUT;
    conv_xw<<<(nconv + 255) / 256, 256>>>(x, Ww);
    adj_pack<<<(BATCH * NN * NN) / 256, 256>>>(adj);
    gemm_mma<<<dim3(HEADS, (BATCH * NN) / 128), 256, GEMM_SMEM>>>(Wb, att);
    attn_mma<<<dim3(NN / 128, HEADS, BATCH), 256, ATTN_SMEM>>>(out);
}

// round 8
// speedup vs baseline: 1.7743x; 1.0918x over previous
#include <cuda_runtime.h>
#include <cuda_bf16.h>
#include <cuda_fp16.h>
#include <math.h>
#include <stdint.h>

// Problem constants: B=8, N=1024, Fin=512, Fout=512, H=8, dh=64
#define BATCH 8
#define NN    1024
#define FIN   512
#define FOUT  512
#define HEADS 8
#define DH    64
#define ALPHA_LR 0.2f

// ---------------- device scratch ----------------
__device__ __nv_bfloat16 g_xh[BATCH * NN * FIN];
__device__ __nv_bfloat16 g_xl[BATCH * NN * FIN];
__device__ __nv_bfloat16 g_wh[FIN * FOUT];
__device__ __nv_bfloat16 g_wl[FIN * FOUT];
__device__ __half        g_hh[BATCH * NN * FOUT];    // h hi (fp16)
__device__ __half        g_hl[BATCH * NN * FOUT];    // h lo (fp16)
__device__ float         g_ssrc[BATCH * HEADS * NN];
__device__ float         g_sdst[BATCH * HEADS * NN];
__device__ unsigned      g_adjbits[BATCH * NN * (NN / 32)];

// ---------------- PTX helpers ----------------
static __device__ __forceinline__ uint32_t smem_u32(const void* p) {
    return (uint32_t)__cvta_generic_to_shared(p);
}
static __device__ __forceinline__ void ldsm_x4(uint32_t* r, uint32_t a) {
    asm volatile("ldmatrix.sync.aligned.m8n8.x4.shared.b16 {%0,%1,%2,%3}, [%4];"
        : "=r"(r[0]), "=r"(r[1]), "=r"(r[2]), "=r"(r[3]) : "r"(a));
}
static __device__ __forceinline__ void ldsm_x4_t(uint32_t* r, uint32_t a) {
    asm volatile("ldmatrix.sync.aligned.m8n8.x4.trans.shared.b16 {%0,%1,%2,%3}, [%4];"
        : "=r"(r[0]), "=r"(r[1]), "=r"(r[2]), "=r"(r[3]) : "r"(a));
}
// bf16 MMA (GEMM)
static __device__ __forceinline__ void mma16816(float* d, const uint32_t* a,
                                                uint32_t b0, uint32_t b1) {
    asm volatile(
        "mma.sync.aligned.m16n8k16.row.col.f32.bf16.bf16.f32 "
        "{%0,%1,%2,%3}, {%4,%5,%6,%7}, {%8,%9}, {%0,%1,%2,%3};"
        : "+f"(d[0]), "+f"(d[1]), "+f"(d[2]), "+f"(d[3])
        : "r"(a[0]), "r"(a[1]), "r"(a[2]), "r"(a[3]), "r"(b0), "r"(b1));
}
// fp16 MMA (attention P*V)
static __device__ __forceinline__ void mma16816h(float* d, const uint32_t* a,
                                                 uint32_t b0, uint32_t b1) {
    asm volatile(
        "mma.sync.aligned.m16n8k16.row.col.f32.f16.f16.f32 "
        "{%0,%1,%2,%3}, {%4,%5,%6,%7}, {%8,%9}, {%0,%1,%2,%3};"
        : "+f"(d[0]), "+f"(d[1]), "+f"(d[2]), "+f"(d[3])
        : "r"(a[0]), "r"(a[1]), "r"(a[2]), "r"(a[3]), "r"(b0), "r"(b1));
}
static __device__ __forceinline__ void cp16(uint32_t dst, const void* src) {
    asm volatile("cp.async.cg.shared.global [%0], [%1], 16;"
        :: "r"(dst), "l"(src) : "memory");
}
static __device__ __forceinline__ void cp4(uint32_t dst, const void* src) {
    asm volatile("cp.async.ca.shared.global [%0], [%1], 4;"
        :: "r"(dst), "l"(src) : "memory");
}
#define CP_COMMIT() asm volatile("cp.async.commit_group;" ::: "memory")
#define CP_WAIT(n)  asm volatile("cp.async.wait_group %0;" :: "n"(n) : "memory")

// masked leakyrelu + exp
static __device__ __forceinline__ float pval(float sd, float s, unsigned m, int bit) {
    float e = sd + s;
    e = fmaxf(e, ALPHA_LR * e);
    float p = __expf(e);
    return ((m >> bit) & 1u) ? p : 0.f;
}
// round to fp16, return rounded float + raw half
static __device__ __forceinline__ float rnd16(float p, __half* q) {
    *q = __float2half_rn(p);
    return __half2float(*q);
}
static __device__ __forceinline__ uint32_t packh2(__half a, __half b) {
    __half2 t = __halves2half2(a, b);
    return *(uint32_t*)&t;
}

// ---------------------------------------------------------------------------
// C0: split X and W into bf16 hi/lo
// ---------------------------------------------------------------------------
__global__ __launch_bounds__(256) void conv_xw(const float* __restrict__ X,
                                               const float* __restrict__ W)
{
    int idx = blockIdx.x * 256 + threadIdx.x;
    const int NX = BATCH * NN * FIN;
    if (idx < NX) {
        float v = X[idx];
        __nv_bfloat16 hi = __float2bfloat16_rn(v);
        g_xh[idx] = hi;
        g_xl[idx] = __float2bfloat16_rn(v - __bfloat162float(hi));
    } else {
        int wi = idx - NX;
        if (wi < FIN * FOUT) {
            float v = W[wi];
            __nv_bfloat16 hi = __float2bfloat16_rn(v);
            g_wh[wi] = hi;
            g_wl[wi] = __float2bfloat16_rn(v - __bfloat162float(hi));
        }
    }
}

// ---------------------------------------------------------------------------
// C1: pack adjacency to bitmask
// ---------------------------------------------------------------------------
__global__ __launch_bounds__(256) void adj_pack(const int* __restrict__ adj)
{
    int e = blockIdx.x * 256 + threadIdx.x;
    unsigned m = __ballot_sync(0xffffffffu, adj[e] > 0);
    if ((threadIdx.x & 31) == 0) g_adjbits[e >> 5] = m;
}

// ---------------------------------------------------------------------------
// K1: split-bf16 MMA GEMM  h = X @ W + b   (3 terms)
// block tile 128m x 64n (one head wide), 8 warps 4m x 2n (warp m32 x n32).
// k-chunks of 16, 2-buffer prefetch-1 cp.async pipeline.
// Epilogue: bias add, write g_hh/g_hl (fp16), fused per-head attention scores.
// ---------------------------------------------------------------------------
#define GB_SZ 16896
#define GM_ATT (2 * GB_SZ)
#define GEMM_SMEM (GM_ATT + 512)
#define G_NCHUNK (FIN / 16)

__global__ __launch_bounds__(256, 3) void gemm_mma(const float* __restrict__ bias,
                                                   const float* __restrict__ att)
{
    extern __shared__ char sp[];
    const uint32_t sb = smem_u32(sp);
    const int tid = threadIdx.x;
    const int w = tid >> 5, lane = tid & 31;
    const int wm = w & 3, wn = w >> 2;          // 4m x 2n warps
    const int bm = blockIdx.y * 128;
    const int hglob = blockIdx.x;               // one head per block
    const int bn = hglob * 64;

    float* sAtt = (float*)(sp + GM_ATT);
    if (tid < 128) sAtt[tid] = att[hglob * 128 + tid];

    auto stage = [&](int c, int buf) {
        const uint32_t bb = sb + buf * GB_SZ;
        int row = tid >> 1, cc = tid & 1;
        size_t asrc = (size_t)(bm + row) * FIN + c * 16 + cc * 8;
        cp16(bb + row * 48 + cc * 16, &g_xh[asrc]);
        cp16(bb + 6144 + row * 48 + cc * 16, &g_xl[asrc]);
        {
            int kind = tid >> 7, u = tid & 127;
            int kr = u >> 3, c2 = u & 7;
            size_t bsrc = (size_t)(c * 16 + kr) * FOUT + bn + c2 * 8;
            cp16(bb + 12288 + kind * 2304 + kr * 144 + c2 * 16,
                 kind ? (const void*)&g_wl[bsrc] : (const void*)&g_wh[bsrc]);
        }
    };

    float acc[2][4][4];
#pragma unroll
    for (int i = 0; i < 2; i++)
#pragma unroll
        for (int j = 0; j < 4; j++)
#pragma unroll
            for (int r = 0; r < 4; r++) acc[i][j][r] = 0.f;

    stage(0, 0); CP_COMMIT();

#pragma unroll 1
    for (int c = 0; c < G_NCHUNK; c++) {
        const int buf = c & 1;
        if (c + 1 < G_NCHUNK) { stage(c + 1, buf ^ 1); CP_COMMIT(); CP_WAIT(1); }
        else CP_WAIT(0);
        __syncthreads();

        const uint32_t bb = sb + buf * GB_SZ;
        uint32_t ah[2][4], al[2][4];
#pragma unroll
        for (int mt = 0; mt < 2; mt++) {
            uint32_t ao = ((wm * 32 + mt * 16 + (lane & 15)) * 24 +
                           (lane >> 4) * 8) * 2;
            ldsm_x4(ah[mt], bb + ao);
            ldsm_x4(al[mt], bb + 6144 + ao);
        }
        const int krow = lane & 15;
#pragma unroll
        for (int p = 0; p < 2; p++) {
            int col = wn * 32 + p * 16 + (lane >> 4) * 8;
            uint32_t bo = (krow * 72 + col) * 2;
            uint32_t bh4[4], bl4[4];
            ldsm_x4_t(bh4, bb + 12288 + bo);
            ldsm_x4_t(bl4, bb + 12288 + 2304 + bo);
#pragma unroll
            for (int mt = 0; mt < 2; mt++) {
                mma16816(acc[mt][2 * p],     ah[mt], bh4[0], bh4[1]);
                mma16816(acc[mt][2 * p],     ah[mt], bl4[0], bl4[1]);
                mma16816(acc[mt][2 * p],     al[mt], bh4[0], bh4[1]);
                mma16816(acc[mt][2 * p + 1], ah[mt], bh4[2], bh4[3]);
                mma16816(acc[mt][2 * p + 1], ah[mt], bl4[2], bl4[3]);
                mma16816(acc[mt][2 * p + 1], al[mt], bh4[2], bh4[3]);
            }
        }
        __syncthreads();
    }

    // -------- epilogue: bias, g_hh/g_hl (fp16), dt stash --------
    float* dt = (float*)sp;                      // 128 x 65 fp32
    const int g = lane >> 2, t = lane & 3;
#pragma unroll
    for (int mt = 0; mt < 2; mt++) {
        const int r0 = wm * 32 + mt * 16 + g;
        const int r1 = r0 + 8;
#pragma unroll
        for (int nt = 0; nt < 4; nt++) {
            int colL = wn * 32 + nt * 8 + 2 * t;
            float2 bv = *(const float2*)&bias[bn + colL];
            float c0 = acc[mt][nt][0] + bv.x;
            float c1 = acc[mt][nt][1] + bv.y;
            float c2 = acc[mt][nt][2] + bv.x;
            float c3 = acc[mt][nt][3] + bv.y;
            dt[r0 * 65 + colL] = c0; dt[r0 * 65 + colL + 1] = c1;
            dt[r1 * 65 + colL] = c2; dt[r1 * 65 + colL + 1] = c3;
            __half h0x = __float2half_rn(c0), h0y = __float2half_rn(c1);
            __half h1x = __float2half_rn(c2), h1y = __float2half_rn(c3);
            __half l0x = __float2half_rn(c0 - __half2float(h0x));
            __half l0y = __float2half_rn(c1 - __half2float(h0y));
            __half l1x = __float2half_rn(c2 - __half2float(h1x));
            __half l1y = __float2half_rn(c3 - __half2float(h1y));
            size_t d0 = (size_t)(bm + r0) * FOUT + bn + colL;
            size_t d1 = (size_t)(bm + r1) * FOUT + bn + colL;
            *(__half2*)&g_hh[d0] = __halves2half2(h0x, h0y);
            *(__half2*)&g_hh[d1] = __halves2half2(h1x, h1y);
            *(__half2*)&g_hl[d0] = __halves2half2(l0x, l0y);
            *(__half2*)&g_hl[d1] = __halves2half2(l1x, l1y);
        }
    }
    __syncthreads();

    // -------- fused scores for this head --------
    {
        const int row = tid >> 1, half = tid & 1;
        float ssum = 0.f, dsum = 0.f;
#pragma unroll 8
        for (int d = half * 32; d < half * 32 + 32; d++) {
            float v = dt[row * 65 + d];
            ssum = fmaf(v, sAtt[d], ssum);
            dsum = fmaf(v, sAtt[64 + d], dsum);
        }
        ssum += __shfl_xor_sync(0xffffffffu, ssum, 1);
        dsum += __shfl_xor_sync(0xffffffffu, dsum, 1);
        if (half == 0) {
            const int nfull = bm + row;
            const int bq = nfull >> 10, n = nfull & 1023;
            g_ssrc[(bq * HEADS + hglob) * NN + n] = ssum;
            g_sdst[(bq * HEADS + hglob) * NN + n] = dsum;
        }
    }
}

// ---------------------------------------------------------------------------
// K3: fused masked softmax + PV (fp16, 2 terms: p*vh + p*vl) + ELU
// block = (b, h, 128 i-rows); 8 warps each own m16 exclusively (warp n64).
// P fragments: fp16 computed DIRECTLY in mma A registers. Denominator is
// accumulated from the fp16-ROUNDED p (softmax-consistent), quad shfl reduce.
// V hi/lo + mask words via 2-buffer prefetch-1 cp.async pipeline.
// ---------------------------------------------------------------------------
#define AB_SZ 9728
#define AT_SS (2 * AB_SZ)
#define ATTN_SMEM (AT_SS + 4096)

__global__ __launch_bounds__(256, 3) void attn_mma(float* __restrict__ out)
{
    extern __shared__ char sp[];
    const uint32_t sb = smem_u32(sp);
    const int b = blockIdx.z, h = blockIdx.y;
    const int i0 = blockIdx.x * 128;
    const int tid = threadIdx.x;
    const int w = tid >> 5, lane = tid & 31;
    const int bh = b * HEADS + h;

    auto stageV = [&](int jt, int buf) {
        const uint32_t bb = sb + buf * AB_SZ;
        int k = tid >> 3, c = tid & 7;
        size_t src = (size_t)(b * NN + jt * 32 + k) * FOUT + h * DH + c * 8;
        cp16(bb + k * 144 + c * 16, &g_hh[src]);
        cp16(bb + 4608 + k * 144 + c * 16, &g_hl[src]);
        if (tid < 128)
            cp4(bb + 9216 + tid * 4,
                &g_adjbits[(size_t)(b * NN + i0 + tid) * (NN / 32) + jt]);
    };

    const int r = lane >> 2;
    const float sd0 = g_sdst[bh * NN + i0 + w * 16 + r];
    const float sd1 = g_sdst[bh * NN + i0 + w * 16 + r + 8];

    cp16(sb + AT_SS + tid * 16, &g_ssrc[bh * NN + tid * 4]);
    stageV(0, 0); CP_COMMIT();

    float acc[8][4];
#pragma unroll
    for (int i = 0; i < 8; i++)
#pragma unroll
        for (int q = 0; q < 4; q++) acc[i][q] = 0.f;
    float den0 = 0.f, den1 = 0.f;

    const float* ssp = (const float*)(sp + AT_SS);
    const int cq = (lane & 3) * 2;

#pragma unroll 1
    for (int jt = 0; jt < NN / 32; jt++) {
        const int buf = jt & 1;
        if (jt + 1 < NN / 32) { stageV(jt + 1, buf ^ 1); CP_COMMIT(); CP_WAIT(1); }
        else CP_WAIT(0);
        __syncthreads();

        const uint32_t bb = sb + buf * AB_SZ;
        const unsigned mw0 = *(const unsigned*)(sp + buf * AB_SZ + 9216 +
                                                (w * 16 + r) * 4);
        const unsigned mw1 = *(const unsigned*)(sp + buf * AB_SZ + 9216 +
                                                (w * 16 + r + 8) * 4);
#pragma unroll
        for (int kc = 0; kc < 2; kc++) {
            const int jb = jt * 32 + kc * 16;
            float2 sA = *(const float2*)&ssp[jb + cq];
            float2 sB = *(const float2*)&ssp[jb + cq + 8];
            const int sh = kc * 16 + cq;
            __half q00, q01, q10, q11, q02, q03, q12, q13;
            den0 += rnd16(pval(sd0, sA.x, mw0, sh),     &q00);
            den0 += rnd16(pval(sd0, sA.y, mw0, sh + 1), &q01);
            den1 += rnd16(pval(sd1, sA.x, mw1, sh),     &q10);
            den1 += rnd16(pval(sd1, sA.y, mw1, sh + 1), &q11);
            den0 += rnd16(pval(sd0, sB.x, mw0, sh + 8), &q02);
            den0 += rnd16(pval(sd0, sB.y, mw0, sh + 9), &q03);
            den1 += rnd16(pval(sd1, sB.x, mw1, sh + 8), &q12);
            den1 += rnd16(pval(sd1, sB.y, mw1, sh + 9), &q13);
            uint32_t ah[4];
            ah[0] = packh2(q00, q01);
            ah[1] = packh2(q10, q11);
            ah[2] = packh2(q02, q03);
            ah[3] = packh2(q12, q13);

            const int krow = kc * 16 + (lane & 15);
#pragma unroll
            for (int nt2 = 0; nt2 < 4; nt2++) {
                int col = nt2 * 16 + (lane >> 4) * 8;
                uint32_t bo = (krow * 72 + col) * 2;
                uint32_t bh4[4], bl4[4];
                ldsm_x4_t(bh4, bb + bo);
                ldsm_x4_t(bl4, bb + 4608 + bo);
                mma16816h(acc[nt2 * 2],     ah, bh4[0], bh4[1]);
                mma16816h(acc[nt2 * 2],     ah, bl4[0], bl4[1]);
                mma16816h(acc[nt2 * 2 + 1], ah, bh4[2], bh4[3]);
                mma16816h(acc[nt2 * 2 + 1], ah, bl4[2], bl4[3]);
            }
        }
        __syncthreads();
    }

    // denominator reduce within quads
    den0 += __shfl_xor_sync(0xffffffffu, den0, 1);
    den0 += __shfl_xor_sync(0xffffffffu, den0, 2);
    den1 += __shfl_xor_sync(0xffffffffu, den1, 1);
    den1 += __shfl_xor_sync(0xffffffffu, den1, 2);
    const float inv0 = 1.f / den0;
    const float inv1 = 1.f / den1;

    // epilogue: normalize, ELU, store
    const size_t row0 = (size_t)(b * NN + i0 + w * 16 + r);
    const size_t row1 = row0 + 8;
#pragma unroll
    for (int nt = 0; nt < 8; nt++) {
        int col = h * DH + nt * 8 + cq;
        float o0 = acc[nt][0] * inv0; o0 = (o0 > 0.f) ? o0 : expm1f(o0);
        float o1 = acc[nt][1] * inv0; o1 = (o1 > 0.f) ? o1 : expm1f(o1);
        float o2 = acc[nt][2] * inv1; o2 = (o2 > 0.f) ? o2 : expm1f(o2);
        float o3 = acc[nt][3] * inv1; o3 = (o3 > 0.f) ? o3 : expm1f(o3);
        *(float2*)&out[row0 * FOUT + col] = make_float2(o0, o1);
        *(float2*)&out[row1 * FOUT + col] = make_float2(o2, o3);
    }
}

// ---------------------------------------------------------------------------
extern "C" void kernel_launch(void* const* d_in, const int* in_sizes, int n_in,
                              void* d_out, int out_size)
{
    const float* x   = (const float*)d_in[0];   // (8,1024,512)
    const int*   adj = (const int*)d_in[1];     // (8,1024,1024)
    const float* Ww  = (const float*)d_in[2];   // (512,512)
    const float* Wb  = (const float*)d_in[3];   // (512,)
    const float* att = (const float*)d_in[4];   // (8,128)
    float* out = (float*)d_out;                 // (8,1024,512)

    cudaFuncSetAttribute(gemm_mma, cudaFuncAttributeMaxDynamicSharedMemorySize,
                         GEMM_SMEM);
    cudaFuncSetAttribute(attn_mma, cudaFuncAttributeMaxDynamicSharedMemorySize,
                         ATTN_SMEM);

    const int nconv = BATCH * NN * FIN + FIN * FOUT;
    conv_xw<<<(nconv + 255) / 256, 256>>>(x, Ww);
    adj_pack<<<(BATCH * NN * NN) / 256, 256>>>(adj);
    gemm_mma<<<dim3(HEADS, (BATCH * NN) / 128), 256, GEMM_SMEM>>>(Wb, att);
    attn_mma<<<dim3(NN / 128, HEADS, BATCH), 256, ATTN_SMEM>>>(out);
}

// round 9
// speedup vs baseline: 2.0789x; 1.1717x over previous
#include <cuda_runtime.h>
#include <cuda_bf16.h>
#include <cuda_fp16.h>
#include <math.h>
#include <stdint.h>

// Problem constants: B=8, N=1024, Fin=512, Fout=512, H=8, dh=64
#define BATCH 8
#define NN    1024
#define FIN   512
#define FOUT  512
#define HEADS 8
#define DH    64
#define ALPHA_LR 0.2f

// ---------------- device scratch ----------------
__device__ __nv_bfloat16 g_xh[BATCH * NN * FIN];
__device__ __nv_bfloat16 g_xl[BATCH * NN * FIN];
__device__ __nv_bfloat16 g_wh[FIN * FOUT];
__device__ __nv_bfloat16 g_wl[FIN * FOUT];
__device__ __half        g_hh[BATCH * NN * FOUT];    // h (fp16, single term)
__device__ float         g_sdst[BATCH * HEADS * NN];
__device__ float2        g_f12[BATCH * HEADS * NN];  // {exp(ss), exp(0.2*ss)}
__device__ unsigned      g_adjbits[BATCH * NN * (NN / 32)];

// ---------------- PTX helpers ----------------
static __device__ __forceinline__ uint32_t smem_u32(const void* p) {
    return (uint32_t)__cvta_generic_to_shared(p);
}
static __device__ __forceinline__ void ldsm_x4(uint32_t* r, uint32_t a) {
    asm volatile("ldmatrix.sync.aligned.m8n8.x4.shared.b16 {%0,%1,%2,%3}, [%4];"
        : "=r"(r[0]), "=r"(r[1]), "=r"(r[2]), "=r"(r[3]) : "r"(a));
}
static __device__ __forceinline__ void ldsm_x4_t(uint32_t* r, uint32_t a) {
    asm volatile("ldmatrix.sync.aligned.m8n8.x4.trans.shared.b16 {%0,%1,%2,%3}, [%4];"
        : "=r"(r[0]), "=r"(r[1]), "=r"(r[2]), "=r"(r[3]) : "r"(a));
}
// bf16 MMA (GEMM)
static __device__ __forceinline__ void mma16816(float* d, const uint32_t* a,
                                                uint32_t b0, uint32_t b1) {
    asm volatile(
        "mma.sync.aligned.m16n8k16.row.col.f32.bf16.bf16.f32 "
        "{%0,%1,%2,%3}, {%4,%5,%6,%7}, {%8,%9}, {%0,%1,%2,%3};"
        : "+f"(d[0]), "+f"(d[1]), "+f"(d[2]), "+f"(d[3])
        : "r"(a[0]), "r"(a[1]), "r"(a[2]), "r"(a[3]), "r"(b0), "r"(b1));
}
// fp16 MMA (attention P*V)
static __device__ __forceinline__ void mma16816h(float* d, const uint32_t* a,
                                                 uint32_t b0, uint32_t b1) {
    asm volatile(
        "mma.sync.aligned.m16n8k16.row.col.f32.f16.f16.f32 "
        "{%0,%1,%2,%3}, {%4,%5,%6,%7}, {%8,%9}, {%0,%1,%2,%3};"
        : "+f"(d[0]), "+f"(d[1]), "+f"(d[2]), "+f"(d[3])
        : "r"(a[0]), "r"(a[1]), "r"(a[2]), "r"(a[3]), "r"(b0), "r"(b1));
}
static __device__ __forceinline__ void cp16(uint32_t dst, const void* src) {
    asm volatile("cp.async.cg.shared.global [%0], [%1], 16;"
        :: "r"(dst), "l"(src) : "memory");
}
static __device__ __forceinline__ void cp4(uint32_t dst, const void* src) {
    asm volatile("cp.async.ca.shared.global [%0], [%1], 4;"
        :: "r"(dst), "l"(src) : "memory");
}
#define CP_COMMIT() asm volatile("cp.async.commit_group;" ::: "memory")
#define CP_WAIT(n)  asm volatile("cp.async.wait_group %0;" :: "n"(n) : "memory")

// pack two fp32 -> fp16x2 (x -> lo, y -> hi)
static __device__ __forceinline__ uint32_t pkh2(float x, float y) {
    uint32_t r;
    asm("cvt.rn.f16x2.f32 %0, %1, %2;" : "=r"(r) : "f"(y), "f"(x));
    return r;
}
// factorized masked leakyrelu-exp: p = (F1 >= T) ? E1*F1 : E2*F2, masked
static __device__ __forceinline__ float psel(float2 f, float T, float E1,
                                             float E2, unsigned m, int bit) {
    float p = (f.x >= T) ? E1 * f.x : E2 * f.y;
    return ((m >> bit) & 1u) ? p : 0.f;
}

// ---------------------------------------------------------------------------
// C0: split X and W into bf16 hi/lo
// ---------------------------------------------------------------------------
__global__ __launch_bounds__(256) void conv_xw(const float* __restrict__ X,
                                               const float* __restrict__ W)
{
    int idx = blockIdx.x * 256 + threadIdx.x;
    const int NX = BATCH * NN * FIN;
    if (idx < NX) {
        float v = X[idx];
        __nv_bfloat16 hi = __float2bfloat16_rn(v);
        g_xh[idx] = hi;
        g_xl[idx] = __float2bfloat16_rn(v - __bfloat162float(hi));
    } else {
        int wi = idx - NX;
        if (wi < FIN * FOUT) {
            float v = W[wi];
            __nv_bfloat16 hi = __float2bfloat16_rn(v);
            g_wh[wi] = hi;
            g_wl[wi] = __float2bfloat16_rn(v - __bfloat162float(hi));
        }
    }
}

// ---------------------------------------------------------------------------
// C1: pack adjacency to bitmask
// ---------------------------------------------------------------------------
__global__ __launch_bounds__(256) void adj_pack(const int* __restrict__ adj)
{
    int e = blockIdx.x * 256 + threadIdx.x;
    unsigned m = __ballot_sync(0xffffffffu, adj[e] > 0);
    if ((threadIdx.x & 31) == 0) g_adjbits[e >> 5] = m;
}

// ---------------------------------------------------------------------------
// K1: split-bf16 MMA GEMM  h = X @ W + b   (3 terms)
// block tile 128m x 64n (one head wide), 8 warps 4m x 2n (warp m32 x n32).
// k-chunks of 16, 2-buffer prefetch-1 cp.async pipeline.
// Epilogue: bias add, write g_hh (fp16), fused scores -> g_sdst + g_f12.
// ---------------------------------------------------------------------------
#define GB_SZ 16896
#define GM_ATT (2 * GB_SZ)
#define GEMM_SMEM (GM_ATT + 512)
#define G_NCHUNK (FIN / 16)

__global__ __launch_bounds__(256, 3) void gemm_mma(const float* __restrict__ bias,
                                                   const float* __restrict__ att)
{
    extern __shared__ char sp[];
    const uint32_t sb = smem_u32(sp);
    const int tid = threadIdx.x;
    const int w = tid >> 5, lane = tid & 31;
    const int wm = w & 3, wn = w >> 2;          // 4m x 2n warps
    const int bm = blockIdx.y * 128;
    const int hglob = blockIdx.x;               // one head per block
    const int bn = hglob * 64;

    float* sAtt = (float*)(sp + GM_ATT);
    if (tid < 128) sAtt[tid] = att[hglob * 128 + tid];

    auto stage = [&](int c, int buf) {
        const uint32_t bb = sb + buf * GB_SZ;
        int row = tid >> 1, cc = tid & 1;
        size_t asrc = (size_t)(bm + row) * FIN + c * 16 + cc * 8;
        cp16(bb + row * 48 + cc * 16, &g_xh[asrc]);
        cp16(bb + 6144 + row * 48 + cc * 16, &g_xl[asrc]);
        {
            int kind = tid >> 7, u = tid & 127;
            int kr = u >> 3, c2 = u & 7;
            size_t bsrc = (size_t)(c * 16 + kr) * FOUT + bn + c2 * 8;
            cp16(bb + 12288 + kind * 2304 + kr * 144 + c2 * 16,
                 kind ? (const void*)&g_wl[bsrc] : (const void*)&g_wh[bsrc]);
        }
    };

    float acc[2][4][4];
#pragma unroll
    for (int i = 0; i < 2; i++)
#pragma unroll
        for (int j = 0; j < 4; j++)
#pragma unroll
            for (int r = 0; r < 4; r++) acc[i][j][r] = 0.f;

    stage(0, 0); CP_COMMIT();

#pragma unroll 1
    for (int c = 0; c < G_NCHUNK; c++) {
        const int buf = c & 1;
        if (c + 1 < G_NCHUNK) { stage(c + 1, buf ^ 1); CP_COMMIT(); CP_WAIT(1); }
        else CP_WAIT(0);
        __syncthreads();

        const uint32_t bb = sb + buf * GB_SZ;
        uint32_t ah[2][4], al[2][4];
#pragma unroll
        for (int mt = 0; mt < 2; mt++) {
            uint32_t ao = ((wm * 32 + mt * 16 + (lane & 15)) * 24 +
                           (lane >> 4) * 8) * 2;
            ldsm_x4(ah[mt], bb + ao);
            ldsm_x4(al[mt], bb + 6144 + ao);
        }
        const int krow = lane & 15;
#pragma unroll
        for (int p = 0; p < 2; p++) {
            int col = wn * 32 + p * 16 + (lane >> 4) * 8;
            uint32_t bo = (krow * 72 + col) * 2;
            uint32_t bh4[4], bl4[4];
            ldsm_x4_t(bh4, bb + 12288 + bo);
            ldsm_x4_t(bl4, bb + 12288 + 2304 + bo);
#pragma unroll
            for (int mt = 0; mt < 2; mt++) {
                mma16816(acc[mt][2 * p],     ah[mt], bh4[0], bh4[1]);
                mma16816(acc[mt][2 * p],     ah[mt], bl4[0], bl4[1]);
                mma16816(acc[mt][2 * p],     al[mt], bh4[0], bh4[1]);
                mma16816(acc[mt][2 * p + 1], ah[mt], bh4[2], bh4[3]);
                mma16816(acc[mt][2 * p + 1], ah[mt], bl4[2], bl4[3]);
                mma16816(acc[mt][2 * p + 1], al[mt], bh4[2], bh4[3]);
            }
        }
        __syncthreads();
    }

    // -------- epilogue: bias, g_hh (fp16), dt stash --------
    float* dt = (float*)sp;                      // 128 x 65 fp32
    const int g = lane >> 2, t = lane & 3;
#pragma unroll
    for (int mt = 0; mt < 2; mt++) {
        const int r0 = wm * 32 + mt * 16 + g;
        const int r1 = r0 + 8;
#pragma unroll
        for (int nt = 0; nt < 4; nt++) {
            int colL = wn * 32 + nt * 8 + 2 * t;
            float2 bv = *(const float2*)&bias[bn + colL];
            float c0 = acc[mt][nt][0] + bv.x;
            float c1 = acc[mt][nt][1] + bv.y;
            float c2 = acc[mt][nt][2] + bv.x;
            float c3 = acc[mt][nt][3] + bv.y;
            dt[r0 * 65 + colL] = c0; dt[r0 * 65 + colL + 1] = c1;
            dt[r1 * 65 + colL] = c2; dt[r1 * 65 + colL + 1] = c3;
            size_t d0 = (size_t)(bm + r0) * FOUT + bn + colL;
            size_t d1 = (size_t)(bm + r1) * FOUT + bn + colL;
            *(__half2*)&g_hh[d0] =
                __halves2half2(__float2half_rn(c0), __float2half_rn(c1));
            *(__half2*)&g_hh[d1] =
                __halves2half2(__float2half_rn(c2), __float2half_rn(c3));
        }
    }
    __syncthreads();

    // -------- fused scores for this head: sdst + factorized src exps --------
    {
        const int row = tid >> 1, half = tid & 1;
        float ssum = 0.f, dsum = 0.f;
#pragma unroll 8
        for (int d = half * 32; d < half * 32 + 32; d++) {
            float v = dt[row * 65 + d];
            ssum = fmaf(v, sAtt[d], ssum);
            dsum = fmaf(v, sAtt[64 + d], dsum);
        }
        ssum += __shfl_xor_sync(0xffffffffu, ssum, 1);
        dsum += __shfl_xor_sync(0xffffffffu, dsum, 1);
        if (half == 0) {
            const int nfull = bm + row;
            const int bq = nfull >> 10, n = nfull & 1023;
            g_sdst[(bq * HEADS + hglob) * NN + n] = dsum;
            g_f12[(bq * HEADS + hglob) * NN + n] =
                make_float2(__expf(ssum), __expf(ALPHA_LR * ssum));
        }
    }
}

// ---------------------------------------------------------------------------
// K3: fused masked softmax + PV (single-term fp16) + ELU
// block = (b, h, 128 i-rows); 8 warps each own m16 exclusively (warp n64).
// P: factorized exp (E_i * F_j) computed directly in fp16 mma A registers.
// V (fp16) + mask words via 2-buffer prefetch-1 cp.async pipeline.
// Denominator: per-thread fp32 sum of own p's, quad shfl reduce.
// smem per buf: Vh 4608 | mask 512 = 5120, x2; F12 8192 @ 10240.
// ---------------------------------------------------------------------------
#define AB_SZ 5120
#define AT_F12 (2 * AB_SZ)
#define ATTN_SMEM (AT_F12 + 8192)

__global__ __launch_bounds__(256, 4) void attn_mma(float* __restrict__ out)
{
    extern __shared__ char sp[];
    const uint32_t sb = smem_u32(sp);
    const int b = blockIdx.z, h = blockIdx.y;
    const int i0 = blockIdx.x * 128;
    const int tid = threadIdx.x;
    const int w = tid >> 5, lane = tid & 31;
    const int bh = b * HEADS + h;

    auto stageV = [&](int jt, int buf) {
        const uint32_t bb = sb + buf * AB_SZ;
        int k = tid >> 3, c = tid & 7;
        size_t src = (size_t)(b * NN + jt * 32 + k) * FOUT + h * DH + c * 8;
        cp16(bb + k * 144 + c * 16, &g_hh[src]);
        if (tid < 128)
            cp4(bb + 4608 + tid * 4,
                &g_adjbits[(size_t)(b * NN + i0 + tid) * (NN / 32) + jt]);
    };

    const int r = lane >> 2;
    const float sd0 = g_sdst[bh * NN + i0 + w * 16 + r];
    const float sd1 = g_sdst[bh * NN + i0 + w * 16 + r + 8];
    const float T0 = __expf(-sd0), E10 = __expf(sd0), E20 = __expf(ALPHA_LR * sd0);
    const float T1 = __expf(-sd1), E11 = __expf(sd1), E21 = __expf(ALPHA_LR * sd1);

    // group 0: F12 table (8KB) + V tile 0 + mask 0
    cp16(sb + AT_F12 + tid * 16, &g_f12[bh * NN + tid * 2]);
    cp16(sb + AT_F12 + 4096 + tid * 16, &g_f12[bh * NN + 512 + tid * 2]);
    stageV(0, 0); CP_COMMIT();

    float acc[8][4];
#pragma unroll
    for (int i = 0; i < 8; i++)
#pragma unroll
        for (int q = 0; q < 4; q++) acc[i][q] = 0.f;
    float den0 = 0.f, den1 = 0.f;

    const float2* fp = (const float2*)(sp + AT_F12);
    const int cq = (lane & 3) * 2;

#pragma unroll 1
    for (int jt = 0; jt < NN / 32; jt++) {
        const int buf = jt & 1;
        if (jt + 1 < NN / 32) { stageV(jt + 1, buf ^ 1); CP_COMMIT(); CP_WAIT(1); }
        else CP_WAIT(0);
        __syncthreads();

        const uint32_t bb = sb + buf * AB_SZ;
        const unsigned mw0 = *(const unsigned*)(sp + buf * AB_SZ + 4608 +
                                                (w * 16 + r) * 4);
        const unsigned mw1 = *(const unsigned*)(sp + buf * AB_SZ + 4608 +
                                                (w * 16 + r + 8) * 4);
#pragma unroll
        for (int kc = 0; kc < 2; kc++) {
            const int jb = jt * 32 + kc * 16;
            float2 fA0 = fp[jb + cq],     fA1 = fp[jb + cq + 1];
            float2 fB0 = fp[jb + cq + 8], fB1 = fp[jb + cq + 9];
            const int sh = kc * 16 + cq;
            float p00 = psel(fA0, T0, E10, E20, mw0, sh);
            float p01 = psel(fA1, T0, E10, E20, mw0, sh + 1);
            float p10 = psel(fA0, T1, E11, E21, mw1, sh);
            float p11 = psel(fA1, T1, E11, E21, mw1, sh + 1);
            float p02 = psel(fB0, T0, E10, E20, mw0, sh + 8);
            float p03 = psel(fB1, T0, E10, E20, mw0, sh + 9);
            float p12 = psel(fB0, T1, E11, E21, mw1, sh + 8);
            float p13 = psel(fB1, T1, E11, E21, mw1, sh + 9);
            den0 += (p00 + p01) + (p02 + p03);
            den1 += (p10 + p11) + (p12 + p13);
            uint32_t ah[4];
            ah[0] = pkh2(p00, p01);
            ah[1] = pkh2(p10, p11);
            ah[2] = pkh2(p02, p03);
            ah[3] = pkh2(p12, p13);

            const int krow = kc * 16 + (lane & 15);
#pragma unroll
            for (int nt2 = 0; nt2 < 4; nt2++) {
                int col = nt2 * 16 + (lane >> 4) * 8;
                uint32_t bh4[4];
                ldsm_x4_t(bh4, bb + (krow * 72 + col) * 2);
                mma16816h(acc[nt2 * 2],     ah, bh4[0], bh4[1]);
                mma16816h(acc[nt2 * 2 + 1], ah, bh4[2], bh4[3]);
            }
        }
        __syncthreads();
    }

    // denominator reduce within quads
    den0 += __shfl_xor_sync(0xffffffffu, den0, 1);
    den0 += __shfl_xor_sync(0xffffffffu, den0, 2);
    den1 += __shfl_xor_sync(0xffffffffu, den1, 1);
    den1 += __shfl_xor_sync(0xffffffffu, den1, 2);
    const float inv0 = 1.f / den0;
    const float inv1 = 1.f / den1;

    // epilogue: normalize, ELU, store
    const size_t row0 = (size_t)(b * NN + i0 + w * 16 + r);
    const size_t row1 = row0 + 8;
#pragma unroll
    for (int nt = 0; nt < 8; nt++) {
        int col = h * DH + nt * 8 + cq;
        float o0 = acc[nt][0] * inv0; o0 = (o0 > 0.f) ? o0 : expm1f(o0);
        float o1 = acc[nt][1] * inv0; o1 = (o1 > 0.f) ? o1 : expm1f(o1);
        float o2 = acc[nt][2] * inv1; o2 = (o2 > 0.f) ? o2 : expm1f(o2);
        float o3 = acc[nt][3] * inv1; o3 = (o3 > 0.f) ? o3 : expm1f(o3);
        *(float2*)&out[row0 * FOUT + col] = make_float2(o0, o1);
        *(float2*)&out[row1 * FOUT + col] = make_float2(o2, o3);
    }
}

// ---------------------------------------------------------------------------
extern "C" void kernel_launch(void* const* d_in, const int* in_sizes, int n_in,
                              void* d_out, int out_size)
{
    const float* x   = (const float*)d_in[0];   // (8,1024,512)
    const int*   adj = (const int*)d_in[1];     // (8,1024,1024)
    const float* Ww  = (const float*)d_in[2];   // (512,512)
    const float* Wb  = (const float*)d_in[3];   // (512,)
    const float* att = (const float*)d_in[4];   // (8,128)
    float* out = (float*)d_out;                 // (8,1024,512)

    cudaFuncSetAttribute(gemm_mma, cudaFuncAttributeMaxDynamicSharedMemorySize,
                         GEMM_SMEM);
    cudaFuncSetAttribute(attn_mma, cudaFuncAttributeMaxDynamicSharedMemorySize,
                         ATTN_SMEM);

    const int nconv = BATCH * NN * FIN + FIN * FOUT;
    conv_xw<<<(nconv + 255) / 256, 256>>>(x, Ww);
    adj_pack<<<(BATCH * NN * NN) / 256, 256>>>(adj);
    gemm_mma<<<dim3(HEADS, (BATCH * NN) / 128), 256, GEMM_SMEM>>>(Wb, att);
    attn_mma<<<dim3(NN / 128, HEADS, BATCH), 256, ATTN_SMEM>>>(out);
}

// round 10
// speedup vs baseline: 2.2600x; 1.0871x over previous
#include <cuda_runtime.h>
#include <cuda_bf16.h>
#include <cuda_fp16.h>
#include <math.h>
#include <stdint.h>

// Problem constants: B=8, N=1024, Fin=512, Fout=512, H=8, dh=64
#define BATCH 8
#define NN    1024
#define FIN   512
#define FOUT  512
#define HEADS 8
#define DH    64
#define ALPHA_LR 0.2f

// ---------------- device scratch ----------------
__device__ __nv_bfloat16 g_xh[BATCH * NN * FIN];
__device__ __nv_bfloat16 g_xl[BATCH * NN * FIN];
__device__ __nv_bfloat16 g_wh[FIN * FOUT];
__device__ __nv_bfloat16 g_wl[FIN * FOUT];
__device__ __half        g_hh[BATCH * NN * FOUT];    // h (fp16)
__device__ float         g_sdst[BATCH * HEADS * NN];
__device__ __half        g_f1[BATCH * HEADS * NN];   // exp(ss) fp16
__device__ __half        g_f2[BATCH * HEADS * NN];   // exp(0.2*ss) fp16
__device__ __half        g_adjh[BATCH * NN * NN];    // adjacency as fp16 0/1

// ---------------- PTX helpers ----------------
static __device__ __forceinline__ uint32_t smem_u32(const void* p) {
    return (uint32_t)__cvta_generic_to_shared(p);
}
static __device__ __forceinline__ void ldsm_x4(uint32_t* r, uint32_t a) {
    asm volatile("ldmatrix.sync.aligned.m8n8.x4.shared.b16 {%0,%1,%2,%3}, [%4];"
        : "=r"(r[0]), "=r"(r[1]), "=r"(r[2]), "=r"(r[3]) : "r"(a));
}
static __device__ __forceinline__ void ldsm_x4_t(uint32_t* r, uint32_t a) {
    asm volatile("ldmatrix.sync.aligned.m8n8.x4.trans.shared.b16 {%0,%1,%2,%3}, [%4];"
        : "=r"(r[0]), "=r"(r[1]), "=r"(r[2]), "=r"(r[3]) : "r"(a));
}
// bf16 MMA (GEMM)
static __device__ __forceinline__ void mma16816(float* d, const uint32_t* a,
                                                uint32_t b0, uint32_t b1) {
    asm volatile(
        "mma.sync.aligned.m16n8k16.row.col.f32.bf16.bf16.f32 "
        "{%0,%1,%2,%3}, {%4,%5,%6,%7}, {%8,%9}, {%0,%1,%2,%3};"
        : "+f"(d[0]), "+f"(d[1]), "+f"(d[2]), "+f"(d[3])
        : "r"(a[0]), "r"(a[1]), "r"(a[2]), "r"(a[3]), "r"(b0), "r"(b1));
}
// fp16 MMA (attention P*V)
static __device__ __forceinline__ void mma16816h(float* d, const uint32_t* a,
                                                 uint32_t b0, uint32_t b1) {
    asm volatile(
        "mma.sync.aligned.m16n8k16.row.col.f32.f16.f16.f32 "
        "{%0,%1,%2,%3}, {%4,%5,%6,%7}, {%8,%9}, {%0,%1,%2,%3};"
        : "+f"(d[0]), "+f"(d[1]), "+f"(d[2]), "+f"(d[3])
        : "r"(a[0]), "r"(a[1]), "r"(a[2]), "r"(a[3]), "r"(b0), "r"(b1));
}
static __device__ __forceinline__ void cp16(uint32_t dst, const void* src) {
    asm volatile("cp.async.cg.shared.global [%0], [%1], 16;"
        :: "r"(dst), "l"(src) : "memory");
}
#define CP_COMMIT() asm volatile("cp.async.commit_group;" ::: "memory")
#define CP_WAIT(n)  asm volatile("cp.async.wait_group %0;" :: "n"(n) : "memory")

// packed p-pair: p = max(E1*F1, E2*F2) * mask   (exp(leakyrelu) identity)
static __device__ __forceinline__ uint32_t ppair(uint32_t f1p, uint32_t f2p,
                                                 __half2 E1, __half2 E2,
                                                 uint32_t mk) {
    __half2 a = __hmul2(E1, *(__half2*)&f1p);
    __half2 b = __hmul2(E2, *(__half2*)&f2p);
    __half2 p = __hmul2(__hmax2(a, b), *(__half2*)&mk);
    return *(uint32_t*)&p;
}
#define ONESH2 0x3C003C00u

// ---------------------------------------------------------------------------
// C0: split X and W into bf16 hi/lo
// ---------------------------------------------------------------------------
__global__ __launch_bounds__(256) void conv_xw(const float* __restrict__ X,
                                               const float* __restrict__ W)
{
    int idx = blockIdx.x * 256 + threadIdx.x;
    const int NX = BATCH * NN * FIN;
    if (idx < NX) {
        float v = X[idx];
        __nv_bfloat16 hi = __float2bfloat16_rn(v);
        g_xh[idx] = hi;
        g_xl[idx] = __float2bfloat16_rn(v - __bfloat162float(hi));
    } else {
        int wi = idx - NX;
        if (wi < FIN * FOUT) {
            float v = W[wi];
            __nv_bfloat16 hi = __float2bfloat16_rn(v);
            g_wh[wi] = hi;
            g_wl[wi] = __float2bfloat16_rn(v - __bfloat162float(hi));
        }
    }
}

// ---------------------------------------------------------------------------
// C1: expand adjacency to fp16 0/1
// ---------------------------------------------------------------------------
__global__ __launch_bounds__(256) void adj_conv(const int* __restrict__ adj)
{
    int idx = blockIdx.x * 256 + threadIdx.x;   // handles 2 elements
    int2 v = ((const int2*)adj)[idx];
    __half2 o = __halves2half2(__int2half_rn(v.x > 0 ? 1 : 0),
                               __int2half_rn(v.y > 0 ? 1 : 0));
    ((__half2*)g_adjh)[idx] = o;
}

// ---------------------------------------------------------------------------
// K1: split-bf16 MMA GEMM  h = X @ W + b   (3 terms)
// block tile 128m x 64n (one head wide), 8 warps 4m x 2n (warp m32 x n32).
// k-chunks of 32, 2-buffer prefetch-1 cp.async pipeline.
// Epilogue: bias add, g_hh (fp16), fused scores -> g_sdst + fp16 F1/F2 tables.
// smem per buf: Ah 10240 | Al 10240 | Bh 4608 | Bl 4608 = 29696, x2 bufs.
// ---------------------------------------------------------------------------
#define GB_SZ 29696
#define GM_ATT (2 * GB_SZ)
#define GEMM_SMEM (GM_ATT + 512)
#define G_NCHUNK (FIN / 32)

__global__ __launch_bounds__(256, 3) void gemm_mma(const float* __restrict__ bias,
                                                   const float* __restrict__ att)
{
    extern __shared__ char sp[];
    const uint32_t sb = smem_u32(sp);
    const int tid = threadIdx.x;
    const int w = tid >> 5, lane = tid & 31;
    const int wm = w & 3, wn = w >> 2;          // 4m x 2n warps
    const int bm = blockIdx.y * 128;
    const int hglob = blockIdx.x;               // one head per block
    const int bn = hglob * 64;

    float* sAtt = (float*)(sp + GM_ATT);
    if (tid < 128) sAtt[tid] = att[hglob * 128 + tid];

    // stage k-chunk c (32 k's): A 128x32 hi/lo (pitch 80B), B 32x64 hi/lo (144B)
    auto stage = [&](int c, int buf) {
        const uint32_t bb = sb + buf * GB_SZ;
#pragma unroll
        for (int s = 0; s < 2; s++) {
            int u = tid * 2 + s;
            int row = u >> 2, q = u & 3;
            size_t asrc = (size_t)(bm + row) * FIN + c * 32 + q * 8;
            cp16(bb + row * 80 + q * 16, &g_xh[asrc]);
            cp16(bb + 10240 + row * 80 + q * 16, &g_xl[asrc]);
        }
        int kr = tid >> 3, c2 = tid & 7;
        size_t bsrc = (size_t)(c * 32 + kr) * FOUT + bn + c2 * 8;
        cp16(bb + 20480 + kr * 144 + c2 * 16, &g_wh[bsrc]);
        cp16(bb + 20480 + 4608 + kr * 144 + c2 * 16, &g_wl[bsrc]);
    };

    float acc[2][4][4];
#pragma unroll
    for (int i = 0; i < 2; i++)
#pragma unroll
        for (int j = 0; j < 4; j++)
#pragma unroll
            for (int r = 0; r < 4; r++) acc[i][j][r] = 0.f;

    stage(0, 0); CP_COMMIT();

#pragma unroll 1
    for (int c = 0; c < G_NCHUNK; c++) {
        const int buf = c & 1;
        if (c + 1 < G_NCHUNK) { stage(c + 1, buf ^ 1); CP_COMMIT(); CP_WAIT(1); }
        else CP_WAIT(0);
        __syncthreads();

        const uint32_t bb = sb + buf * GB_SZ;
#pragma unroll
        for (int kc = 0; kc < 2; kc++) {
            uint32_t ah[2][4], al[2][4];
#pragma unroll
            for (int mt = 0; mt < 2; mt++) {
                uint32_t ao = (wm * 32 + mt * 16 + (lane & 15)) * 80 +
                              kc * 32 + (lane >> 4) * 16;
                ldsm_x4(ah[mt], bb + ao);
                ldsm_x4(al[mt], bb + 10240 + ao);
            }
            const int krow = kc * 16 + (lane & 15);
#pragma unroll
            for (int p = 0; p < 2; p++) {
                int col = wn * 32 + p * 16 + (lane >> 4) * 8;
                uint32_t bo = krow * 144 + col * 2;
                uint32_t bh4[4], bl4[4];
                ldsm_x4_t(bh4, bb + 20480 + bo);
                ldsm_x4_t(bl4, bb + 20480 + 4608 + bo);
#pragma unroll
                for (int mt = 0; mt < 2; mt++) {
                    mma16816(acc[mt][2 * p],     ah[mt], bh4[0], bh4[1]);
                    mma16816(acc[mt][2 * p],     ah[mt], bl4[0], bl4[1]);
                    mma16816(acc[mt][2 * p],     al[mt], bh4[0], bh4[1]);
                    mma16816(acc[mt][2 * p + 1], ah[mt], bh4[2], bh4[3]);
                    mma16816(acc[mt][2 * p + 1], ah[mt], bl4[2], bl4[3]);
                    mma16816(acc[mt][2 * p + 1], al[mt], bh4[2], bh4[3]);
                }
            }
        }
        __syncthreads();
    }

    // -------- epilogue: bias, g_hh (fp16), dt stash --------
    float* dt = (float*)sp;                      // 128 x 65 fp32 (bufs dead)
    const int g = lane >> 2, t = lane & 3;
#pragma unroll
    for (int mt = 0; mt < 2; mt++) {
        const int r0 = wm * 32 + mt * 16 + g;
        const int r1 = r0 + 8;
#pragma unroll
        for (int nt = 0; nt < 4; nt++) {
            int colL = wn * 32 + nt * 8 + 2 * t;
            float2 bv = *(const float2*)&bias[bn + colL];
            float c0 = acc[mt][nt][0] + bv.x;
            float c1 = acc[mt][nt][1] + bv.y;
            float c2 = acc[mt][nt][2] + bv.x;
            float c3 = acc[mt][nt][3] + bv.y;
            dt[r0 * 65 + colL] = c0; dt[r0 * 65 + colL + 1] = c1;
            dt[r1 * 65 + colL] = c2; dt[r1 * 65 + colL + 1] = c3;
            size_t d0 = (size_t)(bm + r0) * FOUT + bn + colL;
            size_t d1 = (size_t)(bm + r1) * FOUT + bn + colL;
            *(__half2*)&g_hh[d0] =
                __halves2half2(__float2half_rn(c0), __float2half_rn(c1));
            *(__half2*)&g_hh[d1] =
                __halves2half2(__float2half_rn(c2), __float2half_rn(c3));
        }
    }
    __syncthreads();

    // -------- fused scores: sdst fp32 + factorized F1/F2 fp16 --------
    {
        const int row = tid >> 1, half = tid & 1;
        float ssum = 0.f, dsum = 0.f;
#pragma unroll 8
        for (int d = half * 32; d < half * 32 + 32; d++) {
            float v = dt[row * 65 + d];
            ssum = fmaf(v, sAtt[d], ssum);
            dsum = fmaf(v, sAtt[64 + d], dsum);
        }
        ssum += __shfl_xor_sync(0xffffffffu, ssum, 1);
        dsum += __shfl_xor_sync(0xffffffffu, dsum, 1);
        if (half == 0) {
            const int nfull = bm + row;
            const int bq = nfull >> 10, n = nfull & 1023;
            const int o = (bq * HEADS + hglob) * NN + n;
            g_sdst[o] = dsum;
            g_f1[o] = __float2half_rn(__expf(ssum));
            g_f2[o] = __float2half_rn(__expf(ALPHA_LR * ssum));
        }
    }
}

// ---------------------------------------------------------------------------
// K3: fused masked softmax + PV (fp16) + ELU
// block = (b, h, 128 i-rows); 8 warps each own m16 exclusively (warp n64).
// p = max(E1*F1, E2*F2) * adjh  -- all packed half2, no branches, no exp.
// Denominator via extra n8 MMA against constant all-ones B fragment.
// V + fp16 adjacency tiles via 2-buffer prefetch-1 cp.async pipeline.
// smem per buf: Vh 4608 | adjh 10240 (pitch 80B) = 14848, x2; F 4096.
// ---------------------------------------------------------------------------
#define AB_SZ 14848
#define AT_F (2 * AB_SZ)
#define ATTN_SMEM (AT_F + 4096)

__global__ __launch_bounds__(256, 4) void attn_mma(float* __restrict__ out)
{
    extern __shared__ char sp[];
    const uint32_t sb = smem_u32(sp);
    const int b = blockIdx.z, h = blockIdx.y;
    const int i0 = blockIdx.x * 128;
    const int tid = threadIdx.x;
    const int w = tid >> 5, lane = tid & 31;
    const int bh = b * HEADS + h;

    auto stageV = [&](int jt, int buf) {
        const uint32_t bb = sb + buf * AB_SZ;
        int k = tid >> 3, c = tid & 7;
        size_t src = (size_t)(b * NN + jt * 32 + k) * FOUT + h * DH + c * 8;
        cp16(bb + k * 144 + c * 16, &g_hh[src]);
#pragma unroll
        for (int s = 0; s < 2; s++) {
            int u = tid * 2 + s;
            int row = u >> 2, seg = u & 3;
            cp16(bb + 4608 + row * 80 + seg * 16,
                 &g_adjh[(size_t)(b * NN + i0 + row) * NN + jt * 32 + seg * 8]);
        }
    };

    const int r = lane >> 2;
    const float sd0 = g_sdst[bh * NN + i0 + w * 16 + r];
    const float sd1 = g_sdst[bh * NN + i0 + w * 16 + r + 8];
    const __half2 E10 = __half2half2(__float2half_rn(__expf(sd0)));
    const __half2 E20 = __half2half2(__float2half_rn(__expf(ALPHA_LR * sd0)));
    const __half2 E11 = __half2half2(__float2half_rn(__expf(sd1)));
    const __half2 E21 = __half2half2(__float2half_rn(__expf(ALPHA_LR * sd1)));

    // group 0: F tables (2KB each) + V/adj tile 0
    if (tid < 128) cp16(sb + AT_F + tid * 16, &g_f1[bh * NN + tid * 8]);
    else cp16(sb + AT_F + 2048 + (tid - 128) * 16, &g_f2[bh * NN + (tid - 128) * 8]);
    stageV(0, 0); CP_COMMIT();

    float acc[8][4];
#pragma unroll
    for (int i = 0; i < 8; i++)
#pragma unroll
        for (int q = 0; q < 4; q++) acc[i][q] = 0.f;
    float accd[4] = {0.f, 0.f, 0.f, 0.f};

    const char* spF = sp + AT_F;
    const int cq = (lane & 3) * 2;

#pragma unroll 1
    for (int jt = 0; jt < NN / 32; jt++) {
        const int buf = jt & 1;
        if (jt + 1 < NN / 32) { stageV(jt + 1, buf ^ 1); CP_COMMIT(); CP_WAIT(1); }
        else CP_WAIT(0);
        __syncthreads();

        const uint32_t bb = sb + buf * AB_SZ;
        const char* mbase = sp + buf * AB_SZ + 4608;
#pragma unroll
        for (int kc = 0; kc < 2; kc++) {
            const int jo = jt * 64 + kc * 32 + cq * 2;   // bytes into F tables
            uint32_t f1A = *(const uint32_t*)(spF + jo);
            uint32_t f1B = *(const uint32_t*)(spF + jo + 16);
            uint32_t f2A = *(const uint32_t*)(spF + 2048 + jo);
            uint32_t f2B = *(const uint32_t*)(spF + 2048 + jo + 16);
            const char* m0 = mbase + (w * 16 + r) * 80 + kc * 32 + cq * 2;
            const char* m1 = m0 + 8 * 80;
            uint32_t ah[4];
            ah[0] = ppair(f1A, f2A, E10, E20, *(const uint32_t*)m0);
            ah[1] = ppair(f1A, f2A, E11, E21, *(const uint32_t*)m1);
            ah[2] = ppair(f1B, f2B, E10, E20, *(const uint32_t*)(m0 + 16));
            ah[3] = ppair(f1B, f2B, E11, E21, *(const uint32_t*)(m1 + 16));

            // denominator: row sums via all-ones B fragment
            mma16816h(accd, ah, ONESH2, ONESH2);

            const int krow = kc * 16 + (lane & 15);
#pragma unroll
            for (int nt2 = 0; nt2 < 4; nt2++) {
                int col = nt2 * 16 + (lane >> 4) * 8;
                uint32_t bh4[4];
                ldsm_x4_t(bh4, bb + (krow * 144 + col * 2));
                mma16816h(acc[nt2 * 2],     ah, bh4[0], bh4[1]);
                mma16816h(acc[nt2 * 2 + 1], ah, bh4[2], bh4[3]);
            }
        }
        __syncthreads();
    }

    const float inv0 = 1.f / accd[0];
    const float inv1 = 1.f / accd[2];

    // epilogue: normalize, ELU, store
    const size_t row0 = (size_t)(b * NN + i0 + w * 16 + r);
    const size_t row1 = row0 + 8;
#pragma unroll
    for (int nt = 0; nt < 8; nt++) {
        int col = h * DH + nt * 8 + cq;
        float o0 = acc[nt][0] * inv0; o0 = (o0 > 0.f) ? o0 : expm1f(o0);
        float o1 = acc[nt][1] * inv0; o1 = (o1 > 0.f) ? o1 : expm1f(o1);
        float o2 = acc[nt][2] * inv1; o2 = (o2 > 0.f) ? o2 : expm1f(o2);
        float o3 = acc[nt][3] * inv1; o3 = (o3 > 0.f) ? o3 : expm1f(o3);
        *(float2*)&out[row0 * FOUT + col] = make_float2(o0, o1);
        *(float2*)&out[row1 * FOUT + col] = make_float2(o2, o3);
    }
}

// ---------------------------------------------------------------------------
extern "C" void kernel_launch(void* const* d_in, const int* in_sizes, int n_in,
                              void* d_out, int out_size)
{
    const float* x   = (const float*)d_in[0];   // (8,1024,512)
    const int*   adj = (const int*)d_in[1];     // (8,1024,1024)
    const float* Ww  = (const float*)d_in[2];   // (512,512)
    const float* Wb  = (const float*)d_in[3];   // (512,)
    const float* att = (const float*)d_in[4];   // (8,128)
    float* out = (float*)d_out;                 // (8,1024,512)

    cudaFuncSetAttribute(gemm_mma, cudaFuncAttributeMaxDynamicSharedMemorySize,
                         GEMM_SMEM);
    cudaFuncSetAttribute(attn_mma, cudaFuncAttributeMaxDynamicSharedMemorySize,
                         ATTN_SMEM);

    const int nconv = BATCH * NN * FIN + FIN * FOUT;
    conv_xw<<<(nconv + 255) / 256, 256>>>(x, Ww);
    adj_conv<<<(BATCH * NN * NN / 2) / 256, 256>>>(adj);
    gemm_mma<<<dim3(HEADS, (BATCH * NN) / 128), 256, GEMM_SMEM>>>(Wb, att);
    attn_mma<<<dim3(NN / 128, HEADS, BATCH), 256, ATTN_SMEM>>>(out);
}

// round 11
// speedup vs baseline: 2.3980x; 1.0611x over previous
#include <cuda_runtime.h>
#include <cuda_bf16.h>
#include <cuda_fp16.h>
#include <math.h>
#include <stdint.h>

// Problem constants: B=8, N=1024, Fin=512, Fout=512, H=8, dh=64
#define BATCH 8
#define NN    1024
#define FIN   512
#define FOUT  512
#define HEADS 8
#define DH    64
#define ALPHA_LR 0.2f

// ---------------- device scratch ----------------
__device__ __nv_bfloat16 g_xh[BATCH * NN * FIN];
__device__ __nv_bfloat16 g_xl[BATCH * NN * FIN];
__device__ __nv_bfloat16 g_wh[FIN * FOUT];
__device__ __nv_bfloat16 g_wl[FIN * FOUT];
__device__ __half        g_hh[BATCH * NN * FOUT];    // h (fp16)
__device__ float         g_sdst[BATCH * HEADS * NN];
__device__ __half        g_f1[BATCH * HEADS * NN];   // exp(ss) fp16
__device__ __half        g_f2[BATCH * HEADS * NN];   // exp(0.2*ss) fp16
__device__ unsigned      g_adjbits[BATCH * NN * (NN / 32)];

// ---------------- PTX helpers ----------------
static __device__ __forceinline__ uint32_t smem_u32(const void* p) {
    return (uint32_t)__cvta_generic_to_shared(p);
}
static __device__ __forceinline__ void ldsm_x4(uint32_t* r, uint32_t a) {
    asm volatile("ldmatrix.sync.aligned.m8n8.x4.shared.b16 {%0,%1,%2,%3}, [%4];"
        : "=r"(r[0]), "=r"(r[1]), "=r"(r[2]), "=r"(r[3]) : "r"(a));
}
static __device__ __forceinline__ void ldsm_x4_t(uint32_t* r, uint32_t a) {
    asm volatile("ldmatrix.sync.aligned.m8n8.x4.trans.shared.b16 {%0,%1,%2,%3}, [%4];"
        : "=r"(r[0]), "=r"(r[1]), "=r"(r[2]), "=r"(r[3]) : "r"(a));
}
// bf16 MMA (GEMM)
static __device__ __forceinline__ void mma16816(float* d, const uint32_t* a,
                                                uint32_t b0, uint32_t b1) {
    asm volatile(
        "mma.sync.aligned.m16n8k16.row.col.f32.bf16.bf16.f32 "
        "{%0,%1,%2,%3}, {%4,%5,%6,%7}, {%8,%9}, {%0,%1,%2,%3};"
        : "+f"(d[0]), "+f"(d[1]), "+f"(d[2]), "+f"(d[3])
        : "r"(a[0]), "r"(a[1]), "r"(a[2]), "r"(a[3]), "r"(b0), "r"(b1));
}
// fp16 MMA (attention P*V)
static __device__ __forceinline__ void mma16816h(float* d, const uint32_t* a,
                                                 uint32_t b0, uint32_t b1) {
    asm volatile(
        "mma.sync.aligned.m16n8k16.row.col.f32.f16.f16.f32 "
        "{%0,%1,%2,%3}, {%4,%5,%6,%7}, {%8,%9}, {%0,%1,%2,%3};"
        : "+f"(d[0]), "+f"(d[1]), "+f"(d[2]), "+f"(d[3])
        : "r"(a[0]), "r"(a[1]), "r"(a[2]), "r"(a[3]), "r"(b0), "r"(b1));
}
static __device__ __forceinline__ void cp16(uint32_t dst, const void* src) {
    asm volatile("cp.async.cg.shared.global [%0], [%1], 16;"
        :: "r"(dst), "l"(src) : "memory");
}
static __device__ __forceinline__ void cp8(uint32_t dst, const void* src) {
    asm volatile("cp.async.ca.shared.global [%0], [%1], 8;"
        :: "r"(dst), "l"(src) : "memory");
}
#define CP_COMMIT() asm volatile("cp.async.commit_group;" ::: "memory")
#define CP_WAIT(n)  asm volatile("cp.async.wait_group %0;" :: "n"(n) : "memory")

// expand bits (sh, sh+1) of w to packed fp16 {b0?1:0, b1?1:0}
static __device__ __forceinline__ uint32_t mkexp(uint32_t w, int sh) {
    uint32_t t = w >> sh;
    return (t & 1u) * 0x3C00u + (t & 2u) * 0x1E000000u;
}
// packed p-pair: p = max(E1*F1, E2*F2) * mask   (exp(leakyrelu) identity)
static __device__ __forceinline__ uint32_t ppair(uint32_t f1p, uint32_t f2p,
                                                 __half2 E1, __half2 E2,
                                                 uint32_t mk) {
    __half2 a = __hmul2(E1, *(__half2*)&f1p);
    __half2 b = __hmul2(E2, *(__half2*)&f2p);
    __half2 p = __hmul2(__hmax2(a, b), *(__half2*)&mk);
    return *(uint32_t*)&p;
}
#define ONESH2 0x3C003C00u

// ---------------------------------------------------------------------------
// C0: split X and W into bf16 hi/lo
// ---------------------------------------------------------------------------
__global__ __launch_bounds__(256) void conv_xw(const float* __restrict__ X,
                                               const float* __restrict__ W)
{
    int idx = blockIdx.x * 256 + threadIdx.x;
    const int NX = BATCH * NN * FIN;
    if (idx < NX) {
        float v = X[idx];
        __nv_bfloat16 hi = __float2bfloat16_rn(v);
        g_xh[idx] = hi;
        g_xl[idx] = __float2bfloat16_rn(v - __bfloat162float(hi));
    } else {
        int wi = idx - NX;
        if (wi < FIN * FOUT) {
            float v = W[wi];
            __nv_bfloat16 hi = __float2bfloat16_rn(v);
            g_wh[wi] = hi;
            g_wl[wi] = __float2bfloat16_rn(v - __bfloat162float(hi));
        }
    }
}

// ---------------------------------------------------------------------------
// C1: pack adjacency to bitmask
// ---------------------------------------------------------------------------
__global__ __launch_bounds__(256) void adj_pack(const int* __restrict__ adj)
{
    int e = blockIdx.x * 256 + threadIdx.x;
    unsigned m = __ballot_sync(0xffffffffu, adj[e] > 0);
    if ((threadIdx.x & 31) == 0) g_adjbits[e >> 5] = m;
}

// ---------------------------------------------------------------------------
// K1: split-bf16 MMA GEMM  h = X @ W + b   (3 terms)
// block tile 128m x 64n (one head wide), 8 warps 4m x 2n (warp m32 x n32).
// k-chunks of 32, 2-buffer prefetch-1 cp.async pipeline.
// Epilogue: bias add, g_hh (fp16), fused scores -> g_sdst + fp16 F1/F2 tables.
// ---------------------------------------------------------------------------
#define GB_SZ 29696
#define GM_ATT (2 * GB_SZ)
#define GEMM_SMEM (GM_ATT + 512)
#define G_NCHUNK (FIN / 32)

__global__ __launch_bounds__(256, 3) void gemm_mma(const float* __restrict__ bias,
                                                   const float* __restrict__ att)
{
    extern __shared__ char sp[];
    const uint32_t sb = smem_u32(sp);
    const int tid = threadIdx.x;
    const int w = tid >> 5, lane = tid & 31;
    const int wm = w & 3, wn = w >> 2;          // 4m x 2n warps
    const int bm = blockIdx.y * 128;
    const int hglob = blockIdx.x;               // one head per block
    const int bn = hglob * 64;

    float* sAtt = (float*)(sp + GM_ATT);
    if (tid < 128) sAtt[tid] = att[hglob * 128 + tid];

    auto stage = [&](int c, int buf) {
        const uint32_t bb = sb + buf * GB_SZ;
#pragma unroll
        for (int s = 0; s < 2; s++) {
            int u = tid * 2 + s;
            int row = u >> 2, q = u & 3;
            size_t asrc = (size_t)(bm + row) * FIN + c * 32 + q * 8;
            cp16(bb + row * 80 + q * 16, &g_xh[asrc]);
            cp16(bb + 10240 + row * 80 + q * 16, &g_xl[asrc]);
        }
        int kr = tid >> 3, c2 = tid & 7;
        size_t bsrc = (size_t)(c * 32 + kr) * FOUT + bn + c2 * 8;
        cp16(bb + 20480 + kr * 144 + c2 * 16, &g_wh[bsrc]);
        cp16(bb + 20480 + 4608 + kr * 144 + c2 * 16, &g_wl[bsrc]);
    };

    float acc[2][4][4];
#pragma unroll
    for (int i = 0; i < 2; i++)
#pragma unroll
        for (int j = 0; j < 4; j++)
#pragma unroll
            for (int r = 0; r < 4; r++) acc[i][j][r] = 0.f;

    stage(0, 0); CP_COMMIT();

#pragma unroll 1
    for (int c = 0; c < G_NCHUNK; c++) {
        const int buf = c & 1;
        if (c + 1 < G_NCHUNK) { stage(c + 1, buf ^ 1); CP_COMMIT(); CP_WAIT(1); }
        else CP_WAIT(0);
        __syncthreads();

        const uint32_t bb = sb + buf * GB_SZ;
#pragma unroll
        for (int kc = 0; kc < 2; kc++) {
            uint32_t ah[2][4], al[2][4];
#pragma unroll
            for (int mt = 0; mt < 2; mt++) {
                uint32_t ao = (wm * 32 + mt * 16 + (lane & 15)) * 80 +
                              kc * 32 + (lane >> 4) * 16;
                ldsm_x4(ah[mt], bb + ao);
                ldsm_x4(al[mt], bb + 10240 + ao);
            }
            const int krow = kc * 16 + (lane & 15);
#pragma unroll
            for (int p = 0; p < 2; p++) {
                int col = wn * 32 + p * 16 + (lane >> 4) * 8;
                uint32_t bo = krow * 144 + col * 2;
                uint32_t bh4[4], bl4[4];
                ldsm_x4_t(bh4, bb + 20480 + bo);
                ldsm_x4_t(bl4, bb + 20480 + 4608 + bo);
#pragma unroll
                for (int mt = 0; mt < 2; mt++) {
                    mma16816(acc[mt][2 * p],     ah[mt], bh4[0], bh4[1]);
                    mma16816(acc[mt][2 * p],     ah[mt], bl4[0], bl4[1]);
                    mma16816(acc[mt][2 * p],     al[mt], bh4[0], bh4[1]);
                    mma16816(acc[mt][2 * p + 1], ah[mt], bh4[2], bh4[3]);
                    mma16816(acc[mt][2 * p + 1], ah[mt], bl4[2], bl4[3]);
                    mma16816(acc[mt][2 * p + 1], al[mt], bh4[2], bh4[3]);
                }
            }
        }
        __syncthreads();
    }

    // -------- epilogue: bias, g_hh (fp16), dt stash --------
    float* dt = (float*)sp;                      // 128 x 65 fp32 (bufs dead)
    const int g = lane >> 2, t = lane & 3;
#pragma unroll
    for (int mt = 0; mt < 2; mt++) {
        const int r0 = wm * 32 + mt * 16 + g;
        const int r1 = r0 + 8;
#pragma unroll
        for (int nt = 0; nt < 4; nt++) {
            int colL = wn * 32 + nt * 8 + 2 * t;
            float2 bv = *(const float2*)&bias[bn + colL];
            float c0 = acc[mt][nt][0] + bv.x;
            float c1 = acc[mt][nt][1] + bv.y;
            float c2 = acc[mt][nt][2] + bv.x;
            float c3 = acc[mt][nt][3] + bv.y;
            dt[r0 * 65 + colL] = c0; dt[r0 * 65 + colL + 1] = c1;
            dt[r1 * 65 + colL] = c2; dt[r1 * 65 + colL + 1] = c3;
            size_t d0 = (size_t)(bm + r0) * FOUT + bn + colL;
            size_t d1 = (size_t)(bm + r1) * FOUT + bn + colL;
            *(__half2*)&g_hh[d0] =
                __halves2half2(__float2half_rn(c0), __float2half_rn(c1));
            *(__half2*)&g_hh[d1] =
                __halves2half2(__float2half_rn(c2), __float2half_rn(c3));
        }
    }
    __syncthreads();

    // -------- fused scores: sdst fp32 + factorized F1/F2 fp16 --------
    {
        const int row = tid >> 1, half = tid & 1;
        float ssum = 0.f, dsum = 0.f;
#pragma unroll 8
        for (int d = half * 32; d < half * 32 + 32; d++) {
            float v = dt[row * 65 + d];
            ssum = fmaf(v, sAtt[d], ssum);
            dsum = fmaf(v, sAtt[64 + d], dsum);
        }
        ssum += __shfl_xor_sync(0xffffffffu, ssum, 1);
        dsum += __shfl_xor_sync(0xffffffffu, dsum, 1);
        if (half == 0) {
            const int nfull = bm + row;
            const int bq = nfull >> 10, n = nfull & 1023;
            const int o = (bq * HEADS + hglob) * NN + n;
            g_sdst[o] = dsum;
            g_f1[o] = __float2half_rn(__expf(ssum));
            g_f2[o] = __float2half_rn(__expf(ALPHA_LR * ssum));
        }
    }
}

// ---------------------------------------------------------------------------
// K3: fused masked softmax + PV (fp16) + ELU
// block = (b, h, 128 i-rows); 8 warps each own m16 exclusively (warp n64).
// 64-j tiles: V (64x64 fp16, pitch 144B) + bitmask rows (8B/row) staged via
// 2-buffer prefetch-1 cp.async; p = max(E1*F1, E2*F2) * bitmask-expanded fp16.
// Denominator via n8 MMA against constant all-ones B fragment.
// smem per buf: V 9216 | mask 1024 = 10240, x2; F tables 4096.
// ---------------------------------------------------------------------------
#define AB_SZ 10240
#define AT_F (2 * AB_SZ)
#define ATTN_SMEM (AT_F + 4096)

__global__ __launch_bounds__(256, 4) void attn_mma(float* __restrict__ out)
{
    extern __shared__ char sp[];
    const uint32_t sb = smem_u32(sp);
    const int b = blockIdx.z, h = blockIdx.y;
    const int i0 = blockIdx.x * 128;
    const int tid = threadIdx.x;
    const int w = tid >> 5, lane = tid & 31;
    const int bh = b * HEADS + h;

    auto stageV = [&](int jt, int buf) {
        const uint32_t bb = sb + buf * AB_SZ;
        int k = tid >> 3, c = tid & 7;
#pragma unroll
        for (int s = 0; s < 2; s++) {
            int row = s * 32 + k;
            size_t src = (size_t)(b * NN + jt * 64 + row) * FOUT + h * DH + c * 8;
            cp16(bb + row * 144 + c * 16, &g_hh[src]);
        }
        if (tid < 128)
            cp8(bb + 9216 + tid * 8,
                &g_adjbits[(size_t)(b * NN + i0 + tid) * (NN / 32) + jt * 2]);
    };

    const int r = lane >> 2;
    const float sd0 = g_sdst[bh * NN + i0 + w * 16 + r];
    const float sd1 = g_sdst[bh * NN + i0 + w * 16 + r + 8];
    const __half2 E10 = __half2half2(__float2half_rn(__expf(sd0)));
    const __half2 E20 = __half2half2(__float2half_rn(__expf(ALPHA_LR * sd0)));
    const __half2 E11 = __half2half2(__float2half_rn(__expf(sd1)));
    const __half2 E21 = __half2half2(__float2half_rn(__expf(ALPHA_LR * sd1)));

    // group 0: F tables (2KB each) + V/mask tile 0
    if (tid < 128) cp16(sb + AT_F + tid * 16, &g_f1[bh * NN + tid * 8]);
    else cp16(sb + AT_F + 2048 + (tid - 128) * 16, &g_f2[bh * NN + (tid - 128) * 8]);
    stageV(0, 0); CP_COMMIT();

    float acc[8][4];
#pragma unroll
    for (int i = 0; i < 8; i++)
#pragma unroll
        for (int q = 0; q < 4; q++) acc[i][q] = 0.f;
    float accd[4] = {0.f, 0.f, 0.f, 0.f};

    const char* spF = sp + AT_F;
    const int cq = (lane & 3) * 2;

#pragma unroll 1
    for (int jt = 0; jt < NN / 64; jt++) {
        const int buf = jt & 1;
        if (jt + 1 < NN / 64) { stageV(jt + 1, buf ^ 1); CP_COMMIT(); CP_WAIT(1); }
        else CP_WAIT(0);
        __syncthreads();

        const uint32_t bb = sb + buf * AB_SZ;
        const uint2 mrow0 = *(const uint2*)(sp + buf * AB_SZ + 9216 +
                                            (w * 16 + r) * 8);
        const uint2 mrow1 = *(const uint2*)(sp + buf * AB_SZ + 9216 +
                                            (w * 16 + r + 8) * 8);
#pragma unroll
        for (int kc = 0; kc < 4; kc++) {
            const uint32_t w0 = (kc < 2) ? mrow0.x : mrow0.y;
            const uint32_t w1 = (kc < 2) ? mrow1.x : mrow1.y;
            const int sh = (kc & 1) * 16 + cq;
            const int jo = jt * 128 + kc * 32 + cq * 2;   // bytes into F tables
            uint32_t f1A = *(const uint32_t*)(spF + jo);
            uint32_t f1B = *(const uint32_t*)(spF + jo + 16);
            uint32_t f2A = *(const uint32_t*)(spF + 2048 + jo);
            uint32_t f2B = *(const uint32_t*)(spF + 2048 + jo + 16);
            uint32_t ah[4];
            ah[0] = ppair(f1A, f2A, E10, E20, mkexp(w0, sh));
            ah[1] = ppair(f1A, f2A, E11, E21, mkexp(w1, sh));
            ah[2] = ppair(f1B, f2B, E10, E20, mkexp(w0, sh + 8));
            ah[3] = ppair(f1B, f2B, E11, E21, mkexp(w1, sh + 8));

            // denominator: row sums via all-ones B fragment
            mma16816h(accd, ah, ONESH2, ONESH2);

            const int krow = kc * 16 + (lane & 15);
#pragma unroll
            for (int nt2 = 0; nt2 < 4; nt2++) {
                int col = nt2 * 16 + (lane >> 4) * 8;
                uint32_t bh4[4];
                ldsm_x4_t(bh4, bb + (krow * 144 + col * 2));
                mma16816h(acc[nt2 * 2],     ah, bh4[0], bh4[1]);
                mma16816h(acc[nt2 * 2 + 1], ah, bh4[2], bh4[3]);
            }
        }
        __syncthreads();
    }

    const float inv0 = 1.f / accd[0];
    const float inv1 = 1.f / accd[2];

    // epilogue: normalize, ELU, store
    const size_t row0 = (size_t)(b * NN + i0 + w * 16 + r);
    const size_t row1 = row0 + 8;
#pragma unroll
    for (int nt = 0; nt < 8; nt++) {
        int col = h * DH + nt * 8 + cq;
        float o0 = acc[nt][0] * inv0; o0 = (o0 > 0.f) ? o0 : expm1f(o0);
        float o1 = acc[nt][1] * inv0; o1 = (o1 > 0.f) ? o1 : expm1f(o1);
        float o2 = acc[nt][2] * inv1; o2 = (o2 > 0.f) ? o2 : expm1f(o2);
        float o3 = acc[nt][3] * inv1; o3 = (o3 > 0.f) ? o3 : expm1f(o3);
        *(float2*)&out[row0 * FOUT + col] = make_float2(o0, o1);
        *(float2*)&out[row1 * FOUT + col] = make_float2(o2, o3);
    }
}

// ---------------------------------------------------------------------------
extern "C" void kernel_launch(void* const* d_in, const int* in_sizes, int n_in,
                              void* d_out, int out_size)
{
    const float* x   = (const float*)d_in[0];   // (8,1024,512)
    const int*   adj = (const int*)d_in[1];     // (8,1024,1024)
    const float* Ww  = (const float*)d_in[2];   // (512,512)
    const float* Wb  = (const float*)d_in[3];   // (512,)
    const float* att = (const float*)d_in[4];   // (8,128)
    float* out = (float*)d_out;                 // (8,1024,512)

    cudaFuncSetAttribute(gemm_mma, cudaFuncAttributeMaxDynamicSharedMemorySize,
                         GEMM_SMEM);
    cudaFuncSetAttribute(attn_mma, cudaFuncAttributeMaxDynamicSharedMemorySize,
                         ATTN_SMEM);

    const int nconv = BATCH * NN * FIN + FIN * FOUT;
    conv_xw<<<(nconv + 255) / 256, 256>>>(x, Ww);
    adj_pack<<<(BATCH * NN * NN) / 256, 256>>>(adj);
    gemm_mma<<<dim3(HEADS, (BATCH * NN) / 128), 256, GEMM_SMEM>>>(Wb, att);
    attn_mma<<<dim3(NN / 128, HEADS, BATCH), 256, ATTN_SMEM>>>(out);
}

// round 12
// speedup vs baseline: 2.4744x; 1.0319x over previous
#include <cuda_runtime.h>
#include <cuda_bf16.h>
#include <cuda_fp16.h>
#include <math.h>
#include <stdint.h>

// Problem constants: B=8, N=1024, Fin=512, Fout=512, H=8, dh=64
#define BATCH 8
#define NN    1024
#define FIN   512
#define FOUT  512
#define HEADS 8
#define DH    64
#define ALPHA_LR 0.2f

// ---------------- device scratch ----------------
__device__ __nv_bfloat16 g_xh[BATCH * NN * FIN];
__device__ __nv_bfloat16 g_xl[BATCH * NN * FIN];
__device__ __nv_bfloat16 g_wh[FIN * FOUT];
__device__ __nv_bfloat16 g_wl[FIN * FOUT];
__device__ __half        g_hh[BATCH * NN * FOUT];    // h (fp16)
__device__ float         g_sdst[BATCH * HEADS * NN];
__device__ __half        g_f1[BATCH * HEADS * NN];   // exp(ss) fp16
__device__ __half        g_f2[BATCH * HEADS * NN];   // exp(0.2*ss) fp16
__device__ unsigned      g_adjbits[BATCH * NN * (NN / 32)];  // nibble-permuted

// ---------------- PTX helpers ----------------
static __device__ __forceinline__ uint32_t smem_u32(const void* p) {
    return (uint32_t)__cvta_generic_to_shared(p);
}
static __device__ __forceinline__ void ldsm_x4(uint32_t* r, uint32_t a) {
    asm volatile("ldmatrix.sync.aligned.m8n8.x4.shared.b16 {%0,%1,%2,%3}, [%4];"
        : "=r"(r[0]), "=r"(r[1]), "=r"(r[2]), "=r"(r[3]) : "r"(a));
}
static __device__ __forceinline__ void ldsm_x4_t(uint32_t* r, uint32_t a) {
    asm volatile("ldmatrix.sync.aligned.m8n8.x4.trans.shared.b16 {%0,%1,%2,%3}, [%4];"
        : "=r"(r[0]), "=r"(r[1]), "=r"(r[2]), "=r"(r[3]) : "r"(a));
}
// bf16 MMA (GEMM)
static __device__ __forceinline__ void mma16816(float* d, const uint32_t* a,
                                                uint32_t b0, uint32_t b1) {
    asm volatile(
        "mma.sync.aligned.m16n8k16.row.col.f32.bf16.bf16.f32 "
        "{%0,%1,%2,%3}, {%4,%5,%6,%7}, {%8,%9}, {%0,%1,%2,%3};"
        : "+f"(d[0]), "+f"(d[1]), "+f"(d[2]), "+f"(d[3])
        : "r"(a[0]), "r"(a[1]), "r"(a[2]), "r"(a[3]), "r"(b0), "r"(b1));
}
// fp16 MMA (attention P*V)
static __device__ __forceinline__ void mma16816h(float* d, const uint32_t* a,
                                                 uint32_t b0, uint32_t b1) {
    asm volatile(
        "mma.sync.aligned.m16n8k16.row.col.f32.f16.f16.f32 "
        "{%0,%1,%2,%3}, {%4,%5,%6,%7}, {%8,%9}, {%0,%1,%2,%3};"
        : "+f"(d[0]), "+f"(d[1]), "+f"(d[2]), "+f"(d[3])
        : "r"(a[0]), "r"(a[1]), "r"(a[2]), "r"(a[3]), "r"(b0), "r"(b1));
}
static __device__ __forceinline__ void cp16(uint32_t dst, const void* src) {
    asm volatile("cp.async.cg.shared.global [%0], [%1], 16;"
        :: "r"(dst), "l"(src) : "memory");
}
#define CP_COMMIT() asm volatile("cp.async.commit_group;" ::: "memory")
#define CP_WAIT(n)  asm volatile("cp.async.wait_group %0;" :: "n"(n) : "memory")

// packed p-pair: p = max(E1*F1, E2*F2) * mask   (exp(leakyrelu) identity)
static __device__ __forceinline__ uint32_t ppair(uint32_t f1p, uint32_t f2p,
                                                 __half2 E1, __half2 E2,
                                                 uint32_t mk) {
    __half2 a = __hmul2(E1, *(__half2*)&f1p);
    __half2 b = __hmul2(E2, *(__half2*)&f2p);
    __half2 p = __hmul2(__hmax2(a, b), *(__half2*)&mk);
    return *(uint32_t*)&p;
}
#define ONESH2 0x3C003C00u

// nibble permutation for adjacency: within each 16-bit half, move bit o to
// position 4*((o&7)>>1) + 2*((o>>3)&1) + (o&1)  -> nibble q holds bits
// {2q, 2q+1, 2q+8, 2q+9}
static __device__ __forceinline__ uint32_t permute_mask(uint32_t m) {
    return (m & 0x00030003u)
         | ((m & 0x000C000Cu) << 2)
         | ((m & 0x00300030u) << 4)
         | ((m & 0x00C000C0u) << 6)
         | ((m & 0x03000300u) >> 6)
         | ((m & 0x0C000C00u) >> 4)
         | ((m & 0x30003000u) >> 2)
         |  (m & 0xC000C000u);
}

// ---------------------------------------------------------------------------
// C0: split X and W into bf16 hi/lo
// ---------------------------------------------------------------------------
__global__ __launch_bounds__(256) void conv_xw(const float* __restrict__ X,
                                               const float* __restrict__ W)
{
    int idx = blockIdx.x * 256 + threadIdx.x;
    const int NX = BATCH * NN * FIN;
    if (idx < NX) {
        float v = X[idx];
        __nv_bfloat16 hi = __float2bfloat16_rn(v);
        g_xh[idx] = hi;
        g_xl[idx] = __float2bfloat16_rn(v - __bfloat162float(hi));
    } else {
        int wi = idx - NX;
        if (wi < FIN * FOUT) {
            float v = W[wi];
            __nv_bfloat16 hi = __float2bfloat16_rn(v);
            g_wh[wi] = hi;
            g_wl[wi] = __float2bfloat16_rn(v - __bfloat162float(hi));
        }
    }
}

// ---------------------------------------------------------------------------
// C1: pack adjacency to nibble-permuted bitmask
// ---------------------------------------------------------------------------
__global__ __launch_bounds__(256) void adj_pack(const int* __restrict__ adj)
{
    int e = blockIdx.x * 256 + threadIdx.x;
    unsigned m = __ballot_sync(0xffffffffu, adj[e] > 0);
    if ((threadIdx.x & 31) == 0) g_adjbits[e >> 5] = permute_mask(m);
}

// ---------------------------------------------------------------------------
// K1: split-bf16 MMA GEMM  h = X @ W + b   (3 terms)
// block tile 128m x 64n (one head wide), 8 warps 4m x 2n (warp m32 x n32).
// k-chunks of 32, 2-buffer prefetch-1 cp.async pipeline.
// A tiles XOR-swizzled (pitch 64B) -> smem 51.2KB -> occupancy 4, single wave.
// Epilogue: bias add, g_hh (fp16), fused scores -> g_sdst + fp16 F1/F2 tables.
// smem per buf: Ah 8192 | Al 8192 | Bh 4608 | Bl 4608 = 25600, x2 bufs.
// ---------------------------------------------------------------------------
#define GB_SZ 25600
#define GM_ATT (2 * GB_SZ)
#define GEMM_SMEM (GM_ATT + 512)
#define G_NCHUNK (FIN / 32)

__global__ __launch_bounds__(256, 4) void gemm_mma(const float* __restrict__ bias,
                                                   const float* __restrict__ att)
{
    extern __shared__ char sp[];
    const uint32_t sb = smem_u32(sp);
    const int tid = threadIdx.x;
    const int w = tid >> 5, lane = tid & 31;
    const int wm = w & 3, wn = w >> 2;          // 4m x 2n warps
    const int bm = blockIdx.y * 128;
    const int hglob = blockIdx.x;               // one head per block
    const int bn = hglob * 64;

    float* sAtt = (float*)(sp + GM_ATT);
    if (tid < 128) sAtt[tid] = att[hglob * 128 + tid];

    auto stage = [&](int c, int buf) {
        const uint32_t bb = sb + buf * GB_SZ;
#pragma unroll
        for (int s = 0; s < 2; s++) {
            int u = tid * 2 + s;
            int row = u >> 2, q = u & 3;
            int swq = q ^ ((row >> 1) & 3);
            size_t asrc = (size_t)(bm + row) * FIN + c * 32 + q * 8;
            cp16(bb + row * 64 + swq * 16, &g_xh[asrc]);
            cp16(bb + 8192 + row * 64 + swq * 16, &g_xl[asrc]);
        }
        int kr = tid >> 3, c2 = tid & 7;
        size_t bsrc = (size_t)(c * 32 + kr) * FOUT + bn + c2 * 8;
        cp16(bb + 16384 + kr * 144 + c2 * 16, &g_wh[bsrc]);
        cp16(bb + 16384 + 4608 + kr * 144 + c2 * 16, &g_wl[bsrc]);
    };

    float acc[2][4][4];
#pragma unroll
    for (int i = 0; i < 2; i++)
#pragma unroll
        for (int j = 0; j < 4; j++)
#pragma unroll
            for (int r = 0; r < 4; r++) acc[i][j][r] = 0.f;

    stage(0, 0); CP_COMMIT();

#pragma unroll 1
    for (int c = 0; c < G_NCHUNK; c++) {
        const int buf = c & 1;
        if (c + 1 < G_NCHUNK) { stage(c + 1, buf ^ 1); CP_COMMIT(); CP_WAIT(1); }
        else CP_WAIT(0);
        __syncthreads();

        const uint32_t bb = sb + buf * GB_SZ;
#pragma unroll
        for (int kc = 0; kc < 2; kc++) {
            uint32_t ah[2][4], al[2][4];
#pragma unroll
            for (int mt = 0; mt < 2; mt++) {
                int mrow = wm * 32 + mt * 16 + (lane & 15);
                int cch = kc * 2 + (lane >> 4);
                uint32_t ao = mrow * 64 + ((cch ^ ((mrow >> 1) & 3)) * 16);
                ldsm_x4(ah[mt], bb + ao);
                ldsm_x4(al[mt], bb + 8192 + ao);
            }
            const int krow = kc * 16 + (lane & 15);
#pragma unroll
            for (int p = 0; p < 2; p++) {
                int col = wn * 32 + p * 16 + (lane >> 4) * 8;
                uint32_t bo = krow * 144 + col * 2;
                uint32_t bh4[4], bl4[4];
                ldsm_x4_t(bh4, bb + 16384 + bo);
                ldsm_x4_t(bl4, bb + 16384 + 4608 + bo);
#pragma unroll
                for (int mt = 0; mt < 2; mt++) {
                    mma16816(acc[mt][2 * p],     ah[mt], bh4[0], bh4[1]);
                    mma16816(acc[mt][2 * p],     ah[mt], bl4[0], bl4[1]);
                    mma16816(acc[mt][2 * p],     al[mt], bh4[0], bh4[1]);
                    mma16816(acc[mt][2 * p + 1], ah[mt], bh4[2], bh4[3]);
                    mma16816(acc[mt][2 * p + 1], ah[mt], bl4[2], bl4[3]);
                    mma16816(acc[mt][2 * p + 1], al[mt], bh4[2], bh4[3]);
                }
            }
        }
        __syncthreads();
    }

    // -------- epilogue: bias, g_hh (fp16), dt stash --------
    float* dt = (float*)sp;                      // 128 x 65 fp32 (bufs dead)
    const int g = lane >> 2, t = lane & 3;
#pragma unroll
    for (int mt = 0; mt < 2; mt++) {
        const int r0 = wm * 32 + mt * 16 + g;
        const int r1 = r0 + 8;
#pragma unroll
        for (int nt = 0; nt < 4; nt++) {
            int colL = wn * 32 + nt * 8 + 2 * t;
            float2 bv = *(const float2*)&bias[bn + colL];
            float c0 = acc[mt][nt][0] + bv.x;
            float c1 = acc[mt][nt][1] + bv.y;
            float c2 = acc[mt][nt][2] + bv.x;
            float c3 = acc[mt][nt][3] + bv.y;
            dt[r0 * 65 + colL] = c0; dt[r0 * 65 + colL + 1] = c1;
            dt[r1 * 65 + colL] = c2; dt[r1 * 65 + colL + 1] = c3;
            size_t d0 = (size_t)(bm + r0) * FOUT + bn + colL;
            size_t d1 = (size_t)(bm + r1) * FOUT + bn + colL;
            *(__half2*)&g_hh[d0] =
                __halves2half2(__float2half_rn(c0), __float2half_rn(c1));
            *(__half2*)&g_hh[d1] =
                __halves2half2(__float2half_rn(c2), __float2half_rn(c3));
        }
    }
    __syncthreads();

    // -------- fused scores: sdst fp32 + factorized F1/F2 fp16 --------
    {
        const int row = tid >> 1, half = tid & 1;
        float ssum = 0.f, dsum = 0.f;
#pragma unroll 8
        for (int d = half * 32; d < half * 32 + 32; d++) {
            float v = dt[row * 65 + d];
            ssum = fmaf(v, sAtt[d], ssum);
            dsum = fmaf(v, sAtt[64 + d], dsum);
        }
        ssum += __shfl_xor_sync(0xffffffffu, ssum, 1);
        dsum += __shfl_xor_sync(0xffffffffu, dsum, 1);
        if (half == 0) {
            const int nfull = bm + row;
            const int bq = nfull >> 10, n = nfull & 1023;
            const int o = (bq * HEADS + hglob) * NN + n;
            g_sdst[o] = dsum;
            g_f1[o] = __float2half_rn(__expf(ssum));
            g_f2[o] = __float2half_rn(__expf(ALPHA_LR * ssum));
        }
    }
}

// ---------------------------------------------------------------------------
// K3: fused masked softmax + PV (fp16) + ELU
// block = (b, h, 128 i-rows); 8 warps each own m16 exclusively (warp n64).
// 128-j tiles: V (128x64 fp16, pitch 144B) + permuted bitmask rows (16B/row)
// via 2-buffer prefetch-1 cp.async. Mask expansion via 16-entry uint2 LUT
// (nibble -> two packed-fp16 0/1 masks). p = max(E1*F1, E2*F2) * mask.
// Denominator via n8 MMA against constant all-ones B fragment.
// smem per buf: V 18432 | mask 2048 = 20480, x2; F tables 4096; LUT 128.
// ---------------------------------------------------------------------------
#define AB_SZ 20480
#define AT_F (2 * AB_SZ)
#define AT_LUT (AT_F + 4096)
#define ATTN_SMEM (AT_LUT + 128)

__global__ __launch_bounds__(256, 4) void attn_mma(float* __restrict__ out)
{
    extern __shared__ char sp[];
    const uint32_t sb = smem_u32(sp);
    const int b = blockIdx.z, h = blockIdx.y;
    const int i0 = blockIdx.x * 128;
    const int tid = threadIdx.x;
    const int w = tid >> 5, lane = tid & 31;
    const int bh = b * HEADS + h;

    // LUT: nibble u -> two packed-fp16 0/1 masks
    if (tid < 16) {
        uint32_t u = tid;
        uint2 v;
        v.x = (u & 1u) * 0x3C00u + ((u >> 1) & 1u) * 0x3C000000u;
        v.y = ((u >> 2) & 1u) * 0x3C00u + ((u >> 3) & 1u) * 0x3C000000u;
        *(uint2*)(sp + AT_LUT + tid * 8) = v;
    }

    auto stageV = [&](int jt, int buf) {
        const uint32_t bb = sb + buf * AB_SZ;
        int k = tid >> 3, c = tid & 7;
#pragma unroll
        for (int s = 0; s < 4; s++) {
            int row = s * 32 + k;
            size_t src = (size_t)(b * NN + jt * 128 + row) * FOUT + h * DH + c * 8;
            cp16(bb + row * 144 + c * 16, &g_hh[src]);
        }
        if (tid < 128)
            cp16(bb + 18432 + tid * 16,
                 &g_adjbits[(size_t)(b * NN + i0 + tid) * (NN / 32) + jt * 4]);
    };

    const int r = lane >> 2;
    const float sd0 = g_sdst[bh * NN + i0 + w * 16 + r];
    const float sd1 = g_sdst[bh * NN + i0 + w * 16 + r + 8];
    const __half2 E10 = __half2half2(__float2half_rn(__expf(sd0)));
    const __half2 E20 = __half2half2(__float2half_rn(__expf(ALPHA_LR * sd0)));
    const __half2 E11 = __half2half2(__float2half_rn(__expf(sd1)));
    const __half2 E21 = __half2half2(__float2half_rn(__expf(ALPHA_LR * sd1)));

    // group 0: F tables (2KB each) + V/mask tile 0
    if (tid < 128) cp16(sb + AT_F + tid * 16, &g_f1[bh * NN + tid * 8]);
    else cp16(sb + AT_F + 2048 + (tid - 128) * 16, &g_f2[bh * NN + (tid - 128) * 8]);
    stageV(0, 0); CP_COMMIT();

    float acc[8][4];
#pragma unroll
    for (int i = 0; i < 8; i++)
#pragma unroll
        for (int q = 0; q < 4; q++) acc[i][q] = 0.f;
    float accd[4] = {0.f, 0.f, 0.f, 0.f};

    const char* spF = sp + AT_F;
    const uint2* lut = (const uint2*)(sp + AT_LUT);
    const int cq = (lane & 3) * 2;
    const int nib = (lane & 3) * 4;             // nibble shift within 16-bit group

#pragma unroll 1
    for (int jt = 0; jt < NN / 128; jt++) {
        const int buf = jt & 1;
        if (jt + 1 < NN / 128) { stageV(jt + 1, buf ^ 1); CP_COMMIT(); CP_WAIT(1); }
        else CP_WAIT(0);
        __syncthreads();

        const uint32_t bb = sb + buf * AB_SZ;
        const uint4 mr0 = *(const uint4*)(sp + buf * AB_SZ + 18432 +
                                          (w * 16 + r) * 16);
        const uint4 mr1 = *(const uint4*)(sp + buf * AB_SZ + 18432 +
                                          (w * 16 + r + 8) * 16);
        const uint32_t mw0[4] = {mr0.x, mr0.y, mr0.z, mr0.w};
        const uint32_t mw1[4] = {mr1.x, mr1.y, mr1.z, mr1.w};
#pragma unroll
        for (int kc = 0; kc < 8; kc++) {
            const int sh4 = (kc & 1) * 16 + nib;
            const uint2 mk0 = lut[(mw0[kc >> 1] >> sh4) & 0xFu];
            const uint2 mk1 = lut[(mw1[kc >> 1] >> sh4) & 0xFu];
            const int jo = jt * 256 + kc * 32 + cq * 2;   // bytes into F tables
            uint32_t f1A = *(const uint32_t*)(spF + jo);
            uint32_t f1B = *(const uint32_t*)(spF + jo + 16);
            uint32_t f2A = *(const uint32_t*)(spF + 2048 + jo);
            uint32_t f2B = *(const uint32_t*)(spF + 2048 + jo + 16);
            uint32_t ah[4];
            ah[0] = ppair(f1A, f2A, E10, E20, mk0.x);
            ah[1] = ppair(f1A, f2A, E11, E21, mk1.x);
            ah[2] = ppair(f1B, f2B, E10, E20, mk0.y);
            ah[3] = ppair(f1B, f2B, E11, E21, mk1.y);

            // denominator: row sums via all-ones B fragment
            mma16816h(accd, ah, ONESH2, ONESH2);

            const int krow = kc * 16 + (lane & 15);
#pragma unroll
            for (int nt2 = 0; nt2 < 4; nt2++) {
                int col = nt2 * 16 + (lane >> 4) * 8;
                uint32_t bh4[4];
                ldsm_x4_t(bh4, bb + (krow * 144 + col * 2));
                mma16816h(acc[nt2 * 2],     ah, bh4[0], bh4[1]);
                mma16816h(acc[nt2 * 2 + 1], ah, bh4[2], bh4[3]);
            }
        }
        __syncthreads();
    }

    const float inv0 = 1.f / accd[0];
    const float inv1 = 1.f / accd[2];

    // epilogue: normalize, ELU, store
    const size_t row0 = (size_t)(b * NN + i0 + w * 16 + r);
    const size_t row1 = row0 + 8;
#pragma unroll
    for (int nt = 0; nt < 8; nt++) {
        int col = h * DH + nt * 8 + cq;
        float o0 = acc[nt][0] * inv0; o0 = (o0 > 0.f) ? o0 : expm1f(o0);
        float o1 = acc[nt][1] * inv0; o1 = (o1 > 0.f) ? o1 : expm1f(o1);
        float o2 = acc[nt][2] * inv1; o2 = (o2 > 0.f) ? o2 : expm1f(o2);
        float o3 = acc[nt][3] * inv1; o3 = (o3 > 0.f) ? o3 : expm1f(o3);
        *(float2*)&out[row0 * FOUT + col] = make_float2(o0, o1);
        *(float2*)&out[row1 * FOUT + col] = make_float2(o2, o3);
    }
}

// ---------------------------------------------------------------------------
extern "C" void kernel_launch(void* const* d_in, const int* in_sizes, int n_in,
                              void* d_out, int out_size)
{
    const float* x   = (const float*)d_in[0];   // (8,1024,512)
    const int*   adj = (const int*)d_in[1];     // (8,1024,1024)
    const float* Ww  = (const float*)d_in[2];   // (512,512)
    const float* Wb  = (const float*)d_in[3];   // (512,)
    const float* att = (const float*)d_in[4];   // (8,128)
    float* out = (float*)d_out;                 // (8,1024,512)

    cudaFuncSetAttribute(gemm_mma, cudaFuncAttributeMaxDynamicSharedMemorySize,
                         GEMM_SMEM);
    cudaFuncSetAttribute(attn_mma, cudaFuncAttributeMaxDynamicSharedMemorySize,
                         ATTN_SMEM);

    const int nconv = BATCH * NN * FIN + FIN * FOUT;
    conv_xw<<<(nconv + 255) / 256, 256>>>(x, Ww);
    adj_pack<<<(BATCH * NN * NN) / 256, 256>>>(adj);
    gemm_mma<<<dim3(HEADS, (BATCH * NN) / 128), 256, GEMM_SMEM>>>(Wb, att);
    attn_mma<<<dim3(NN / 128, HEADS, BATCH), 256, ATTN_SMEM>>>(out);
}